// round 8
// baseline (speedup 1.0000x reference)
#include <cuda_runtime.h>
#include <cuda_fp16.h>
#include <cstdint>

// Problem dims
#define BATCH 4
#define SEQ   2048
#define EMBED 1024
#define HID   4096
#define VOCAB 32000

// ---------------------------------------------------------------------------
// PTX helpers (plain sm_103-legal: cp.async / ldmatrix / mma.sync only)
// ---------------------------------------------------------------------------
__device__ __forceinline__ uint32_t smem_u32(const void* p) {
    uint32_t a;
    asm("{ .reg .u64 t; cvta.to.shared.u64 t, %1; cvt.u32.u64 %0, t; }" : "=r"(a) : "l"(p));
    return a;
}
#define CP_ASYNC16(s, g) \
    asm volatile("cp.async.cg.shared.global [%0], [%1], 16;\n" :: "r"(s), "l"(g))
#define CP_COMMIT() asm volatile("cp.async.commit_group;\n" ::: "memory")
#define CP_WAIT1()  asm volatile("cp.async.wait_group 1;\n" ::: "memory")
#define CP_WAIT2()  asm volatile("cp.async.wait_group 2;\n" ::: "memory")

__device__ __forceinline__ void ldsm4(uint32_t* r, uint32_t a) {
    asm volatile("ldmatrix.sync.aligned.m8n8.x4.shared.b16 {%0,%1,%2,%3}, [%4];"
        : "=r"(r[0]), "=r"(r[1]), "=r"(r[2]), "=r"(r[3]) : "r"(a));
}
__device__ __forceinline__ void mma16816(float* c, const uint32_t* a, const uint32_t* b) {
    asm volatile(
        "mma.sync.aligned.m16n8k16.row.col.f32.f16.f16.f32 "
        "{%0,%1,%2,%3}, {%4,%5,%6,%7}, {%8,%9}, {%0,%1,%2,%3};"
        : "+f"(c[0]), "+f"(c[1]), "+f"(c[2]), "+f"(c[3])
        : "r"(a[0]), "r"(a[1]), "r"(a[2]), "r"(a[3]), "r"(b[0]), "r"(b[1]));
}

// 128B-row SW128 swizzle: row r, 16B-chunk q (0..7) -> byte offset in tile
#define SWZ(r, q) ((uint32_t)((r) * 128 + ((((q) ^ ((r) & 7))) << 4)))

// fp16 hi/lo split (hi+lo covers ~22 mantissa bits of the fp32 value)
__device__ __forceinline__ void hsplit(float v, __half& h, __half& l) {
    h = __float2half_rn(v);
    l = __float2half_rn(v - __half2float(h));
}

// ---------------------------------------------------------------------------
// Scratch (device globals)
// ---------------------------------------------------------------------------
__device__ float  g_x     [BATCH * SEQ * EMBED];
__device__ __half g_xhi   [BATCH * SEQ * EMBED];
__device__ __half g_xlo   [BATCH * SEQ * EMBED];
__device__ __half g_xThi  [BATCH * EMBED * SEQ];
__device__ __half g_xTlo  [BATCH * EMBED * SEQ];
__device__ float  g_scores[BATCH * SEQ * SEQ];
__device__ __half g_whi   [BATCH * SEQ * SEQ];
__device__ __half g_wlo   [BATCH * SEQ * SEQ];
__device__ __half g_atthi [BATCH * SEQ * EMBED];
__device__ __half g_attlo [BATCH * SEQ * EMBED];
__device__ __half g_hidhi [BATCH * SEQ * HID];
__device__ __half g_W1t   [HID * EMBED];
__device__ __half g_W2t   [(size_t)VOCAB * HID];

// ---------------------------------------------------------------------------
// Embedding gather: x fp32 + fp16 hi/lo
// ---------------------------------------------------------------------------
__global__ void embed_kernel(const int* __restrict__ ids, const float* __restrict__ emb,
                             float* __restrict__ x,
                             __half* __restrict__ xhi, __half* __restrict__ xlo) {
    int row = blockIdx.x;
    int id  = ids[row];
    int t = threadIdx.x;
    float4 v = reinterpret_cast<const float4*>(emb + (long)id * EMBED)[t];
    reinterpret_cast<float4*>(x + (long)row * EMBED)[t] = v;
    __half h0, l0, h1, l1, h2, l2, h3, l3;
    hsplit(v.x, h0, l0); hsplit(v.y, h1, l1); hsplit(v.z, h2, l2); hsplit(v.w, h3, l3);
    __half2* dh = reinterpret_cast<__half2*>(xhi + (long)row * EMBED) + t * 2;
    __half2* dl = reinterpret_cast<__half2*>(xlo + (long)row * EMBED) + t * 2;
    dh[0] = __halves2half2(h0, h1); dh[1] = __halves2half2(h2, h3);
    dl[0] = __halves2half2(l0, l1); dl[1] = __halves2half2(l2, l3);
}

// ---------------------------------------------------------------------------
// Transpose fp32 [R,C] -> fp16 [C,R] hi/lo, batched via z (for xT)
// ---------------------------------------------------------------------------
__global__ void transpose_split_kernel(const float* __restrict__ in,
                                       __half* __restrict__ ohi, __half* __restrict__ olo,
                                       int R, int C, long sIn, long sOut) {
    __shared__ float t[32][33];
    long z = blockIdx.z;
    in  += z * sIn;
    ohi += z * sOut; olo += z * sOut;
    int c0 = blockIdx.x * 32, r0 = blockIdx.y * 32;
    int tx = threadIdx.x, ty = threadIdx.y;
    #pragma unroll
    for (int i = 0; i < 32; i += 8)
        t[ty + i][tx] = in[(long)(r0 + ty + i) * C + c0 + tx];
    __syncthreads();
    #pragma unroll
    for (int i = 0; i < 32; i += 8) {
        float v = t[tx][ty + i];
        __half h, l; hsplit(v, h, l);
        long o = (long)(c0 + ty + i) * R + r0 + tx;
        ohi[o] = h; olo[o] = l;
    }
}

// ---------------------------------------------------------------------------
// Combined weight transpose: z=0 -> W1 [E,H] -> w1t [H,E]
//                            z=1 -> W2 [H,V] -> w2t [V,H]
// ---------------------------------------------------------------------------
__global__ void transpose_weights_kernel(const float* __restrict__ W1,
                                         const float* __restrict__ W2,
                                         __half* __restrict__ w1t,
                                         __half* __restrict__ w2t) {
    __shared__ float t[32][33];
    const float* in; __half* outp; int R, C;
    if (blockIdx.z == 0) {
        if (blockIdx.x >= HID / 32 || blockIdx.y >= EMBED / 32) return;
        in = W1; outp = w1t; R = EMBED; C = HID;
    } else {
        in = W2; outp = w2t; R = HID; C = VOCAB;
    }
    int c0 = blockIdx.x * 32, r0 = blockIdx.y * 32;
    int tx = threadIdx.x, ty = threadIdx.y;
    #pragma unroll
    for (int i = 0; i < 32; i += 8)
        t[ty + i][tx] = in[(long)(r0 + ty + i) * C + c0 + tx];
    __syncthreads();
    #pragma unroll
    for (int i = 0; i < 32; i += 8) {
        long o = (long)(c0 + ty + i) * R + r0 + tx;
        outp[o] = __float2half_rn(t[tx][ty + i]);
    }
}

// ---------------------------------------------------------------------------
// Softmax rows (fp32 in) -> fp16 hi/lo weights
// ---------------------------------------------------------------------------
__global__ __launch_bounds__(256)
void softmax_kernel(const float* __restrict__ scores,
                    __half* __restrict__ whi, __half* __restrict__ wlo) {
    __shared__ float red[256];
    const float* row = scores + (long)blockIdx.x * SEQ;
    __half* oh = whi + (long)blockIdx.x * SEQ;
    __half* ol = wlo + (long)blockIdx.x * SEQ;
    const int tid = threadIdx.x;

    float v[8];
    float lmax = -3.402823466e+38f;
    #pragma unroll
    for (int i = 0; i < 8; i++) { v[i] = row[tid + i * 256]; lmax = fmaxf(lmax, v[i]); }
    red[tid] = lmax; __syncthreads();
    #pragma unroll
    for (int s = 128; s > 0; s >>= 1) { if (tid < s) red[tid] = fmaxf(red[tid], red[tid + s]); __syncthreads(); }
    float m = red[0]; __syncthreads();

    float lsum = 0.f;
    #pragma unroll
    for (int i = 0; i < 8; i++) { v[i] = __expf(v[i] - m); lsum += v[i]; }
    red[tid] = lsum; __syncthreads();
    #pragma unroll
    for (int s = 128; s > 0; s >>= 1) { if (tid < s) red[tid] += red[tid + s]; __syncthreads(); }
    float inv = 1.f / red[0];
    #pragma unroll
    for (int i = 0; i < 8; i++) {
        float w = v[i] * inv;
        __half h, l; hsplit(w, h, l);
        oh[tid + i * 256] = h; ol[tid + i * 256] = l;
    }
}

// ---------------------------------------------------------------------------
// HMMA split-fp16 GEMM (attention + FFN1):  C[M,N] = A[M,K] * B[N,K]^T
// MODE=2: A0*B0 + A1*B0.  MODE=3: + A0*B1.
// OUT=0: fp32 (+bias,+relu)   OUT=1: fp16 hi only   OUT=2: fp16 hi/lo
// CTA 128x128, BK=64 (SW128 rows), 8 warps, 3 stages, reg double-buffered.
// ---------------------------------------------------------------------------
#define BMT 128
#define BNT 128
#define BKT 64
#define NSTAGE 3
#define TILE_BYTES 16384    // 128 rows x 128 B

template<int TPS>
__device__ __forceinline__ void load_chunk(uint32_t sbase, int st,
    const __half* __restrict__ gA0, const __half* __restrict__ gA1,
    const __half* __restrict__ gB0, const __half* __restrict__ gB1,
    int K, int k0, int tid)
{
    uint32_t s0 = sbase + (uint32_t)(st * TPS * TILE_BYTES);
    #pragma unroll
    for (int it = 0; it < 4; it++) {
        int idx = tid + it * 256;
        int r = idx >> 3, c = idx & 7;
        uint32_t so = SWZ(r, c);
        long go = (long)r * K + k0 + c * 8;
        CP_ASYNC16(s0 + 0 * TILE_BYTES + so, gA0 + go);
        CP_ASYNC16(s0 + 1 * TILE_BYTES + so, gA1 + go);
        CP_ASYNC16(s0 + 2 * TILE_BYTES + so, gB0 + go);
        if (TPS == 4) CP_ASYNC16(s0 + 3 * TILE_BYTES + so, gB1 + go);
    }
}

template<int MODE, int OUT, bool BIAS, bool RELU>
__global__ __launch_bounds__(256)
void hgemm(const __half* __restrict__ A0, const __half* __restrict__ A1,
           const __half* __restrict__ B0, const __half* __restrict__ B1,
           const float* __restrict__ bias,
           float* __restrict__ Cf, __half* __restrict__ Chi, __half* __restrict__ Clo,
           int M, int N, int K, long sA, long sB, long sC, int ntm)
{
    extern __shared__ char smem[];
    const uint32_t sbase = smem_u32(smem);
    const int tid  = threadIdx.x;
    const int wid  = tid >> 5, lane = tid & 31;
    const int wm   = wid & 1,  wn   = wid >> 1;
    constexpr int TPS = (MODE == 3) ? 4 : 3;

    int pm = blockIdx.x % ntm, pn = blockIdx.x / ntm;
    long m0 = (long)pm * BMT, n0 = (long)pn * BNT;
    long zb = blockIdx.z;
    const __half* gA0 = A0 + zb * sA + m0 * K;
    const __half* gA1 = A1 + zb * sA + m0 * K;
    const __half* gB0 = B0 + zb * sB + n0 * K;
    const __half* gB1 = (MODE == 3) ? (B1 + zb * sB + n0 * K) : gB0;

    float acc[4][4][4];
    #pragma unroll
    for (int i = 0; i < 4; i++)
        #pragma unroll
        for (int j = 0; j < 4; j++)
            #pragma unroll
            for (int k = 0; k < 4; k++) acc[i][j][k] = 0.f;

    uint32_t a0f[2][4][4], a1f[2][4][4], b0f[2][2][4], b1f[2][2][4];
    const int ar = lane & 15;
    const int ak = (lane >> 4) << 3;
    const int br = ((lane >> 4) << 3) + (lane & 7);
    const int bk = ((lane >> 3) & 1) << 3;

    auto load_frags = [&](uint32_t s0, int kb, int buf) {
        int aq = (kb + ak) >> 3;
        int bq = (kb + bk) >> 3;
        #pragma unroll
        for (int mt = 0; mt < 4; mt++) {
            int r = wm * 64 + mt * 16 + ar;
            uint32_t ad = s0 + SWZ(r, aq);
            ldsm4(a0f[buf][mt], ad);
            ldsm4(a1f[buf][mt], ad + TILE_BYTES);
        }
        #pragma unroll
        for (int nt = 0; nt < 2; nt++) {
            int r = wn * 32 + nt * 16 + br;
            uint32_t bd = s0 + 2 * TILE_BYTES + SWZ(r, bq);
            ldsm4(b0f[buf][nt], bd);
            if (MODE == 3) ldsm4(b1f[buf][nt], bd + TILE_BYTES);
        }
    };

    load_chunk<TPS>(sbase, 0, gA0, gA1, gB0, gB1, K, 0, tid);   CP_COMMIT();
    load_chunk<TPS>(sbase, 1, gA0, gA1, gB0, gB1, K, BKT, tid); CP_COMMIT();

    const int nc = K / BKT;
    for (int c = 0; c < nc; c++) {
        CP_WAIT1();
        __syncthreads();
        if (c + 2 < nc)
            load_chunk<TPS>(sbase, (c + 2) % NSTAGE, gA0, gA1, gB0, gB1, K, (c + 2) * BKT, tid);
        CP_COMMIT();

        uint32_t s0 = sbase + (uint32_t)((c % NSTAGE) * TPS * TILE_BYTES);
        load_frags(s0, 0, 0);
        #pragma unroll
        for (int kb4 = 0; kb4 < 4; kb4++) {
            int cur = kb4 & 1;
            if (kb4 < 3) load_frags(s0, (kb4 + 1) * 16, cur ^ 1);
            #pragma unroll
            for (int mt = 0; mt < 4; mt++)
                #pragma unroll
                for (int n8 = 0; n8 < 4; n8++) {
                    const uint32_t* b = &b0f[cur][n8 >> 1][(n8 & 1) * 2];
                    mma16816(acc[mt][n8], a0f[cur][mt], b);
                    mma16816(acc[mt][n8], a1f[cur][mt], b);
                    if (MODE == 3)
                        mma16816(acc[mt][n8], a0f[cur][mt], &b1f[cur][n8 >> 1][(n8 & 1) * 2]);
                }
        }
    }

    // ---- epilogue ----
    long zC = zb * sC;
    int rb = lane >> 2;
    int cb = (lane & 3) * 2;
    #pragma unroll
    for (int mt = 0; mt < 4; mt++) {
        #pragma unroll
        for (int n8 = 0; n8 < 4; n8++) {
            long col = n0 + wn * 32 + n8 * 8 + cb;
            float bv0 = 0.f, bv1 = 0.f;
            if (BIAS) { bv0 = bias[col]; bv1 = bias[col + 1]; }
            #pragma unroll
            for (int h = 0; h < 2; h++) {
                long row = m0 + wm * 64 + mt * 16 + rb + h * 8;
                float v0 = acc[mt][n8][h * 2 + 0] + bv0;
                float v1 = acc[mt][n8][h * 2 + 1] + bv1;
                if (RELU) { v0 = fmaxf(v0, 0.f); v1 = fmaxf(v1, 0.f); }
                long o = row * (long)N + col;
                if (OUT == 0) {
                    *reinterpret_cast<float2*>(Cf + zC + o) = make_float2(v0, v1);
                } else if (OUT == 1) {
                    *reinterpret_cast<__half2*>(Chi + zC + o) =
                        __halves2half2(__float2half_rn(v0), __float2half_rn(v1));
                } else {
                    __half h0, l0, h1, l1;
                    hsplit(v0, h0, l0); hsplit(v1, h1, l1);
                    *reinterpret_cast<__half2*>(Chi + zC + o) = __halves2half2(h0, h1);
                    *reinterpret_cast<__half2*>(Clo + zC + o) = __halves2half2(l0, l1);
                }
            }
        }
    }
}

// ---------------------------------------------------------------------------
// FFN2 GEMM: 512 threads, CTA 128x256, warp tile 64x32 (2x8 warp grid),
// BK=64, 4 stages, single-buffered frags (~115 regs -> fits 512 thr in RF).
// 16 warps = 4 eligible warps per SMSP to keep the tensor pipe fed.
// ---------------------------------------------------------------------------
#define WNS 4
#define W_ABYTES 16384             // 128 x 128 B
#define W_BBYTES 32768             // 256 x 128 B
#define W_STAGE  (W_ABYTES + W_BBYTES)

__device__ __forceinline__ void load_chunk_wide(uint32_t sbase, int st,
    const __half* __restrict__ gA, const __half* __restrict__ gB,
    int K, int k0, int tid)
{
    uint32_t s0 = sbase + (uint32_t)(st * W_STAGE);
    #pragma unroll
    for (int it = 0; it < 2; it++) {
        int idx = tid + it * 512;
        int r = idx >> 3, c = idx & 7;
        CP_ASYNC16(s0 + SWZ(r, c), gA + (long)r * K + k0 + c * 8);
    }
    #pragma unroll
    for (int it = 0; it < 4; it++) {
        int idx = tid + it * 512;
        int r = idx >> 3, c = idx & 7;
        CP_ASYNC16(s0 + W_ABYTES + SWZ(r, c), gB + (long)r * K + k0 + c * 8);
    }
}

template<bool BIAS>
__global__ __launch_bounds__(512, 1)
void hgemm_ffn2(const __half* __restrict__ A0, const __half* __restrict__ B0,
                const float* __restrict__ bias, float* __restrict__ Cf,
                int M, int N, int K, int ntm)
{
    extern __shared__ char smem[];
    const uint32_t sbase = smem_u32(smem);
    const int tid  = threadIdx.x;
    const int wid  = tid >> 5, lane = tid & 31;
    const int wm   = wid & 1,  wn   = wid >> 1;   // 2 x 8 warp grid

    int pm = blockIdx.x % ntm, pn = blockIdx.x / ntm;
    long m0 = (long)pm * 128, n0 = (long)pn * 256;
    const __half* gA = A0 + m0 * K;
    const __half* gB = B0 + n0 * K;

    float acc[4][4][4];
    #pragma unroll
    for (int i = 0; i < 4; i++)
        #pragma unroll
        for (int j = 0; j < 4; j++)
            #pragma unroll
            for (int k = 0; k < 4; k++) acc[i][j][k] = 0.f;

    const int ar = lane & 15;
    const int ak = (lane >> 4) << 3;
    const int br = ((lane >> 4) << 3) + (lane & 7);
    const int bk = ((lane >> 3) & 1) << 3;

    load_chunk_wide(sbase, 0, gA, gB, K, 0, tid);        CP_COMMIT();
    load_chunk_wide(sbase, 1, gA, gB, K, BKT, tid);      CP_COMMIT();
    load_chunk_wide(sbase, 2, gA, gB, K, 2 * BKT, tid);  CP_COMMIT();

    const int nc = K / BKT;
    for (int c = 0; c < nc; c++) {
        CP_WAIT2();
        __syncthreads();
        if (c + 3 < nc)
            load_chunk_wide(sbase, (c + 3) % WNS, gA, gB, K, (c + 3) * BKT, tid);
        CP_COMMIT();

        uint32_t s0 = sbase + (uint32_t)((c % WNS) * W_STAGE);
        #pragma unroll
        for (int kb = 0; kb < BKT; kb += 16) {
            uint32_t af[4][4], bf[2][4];
            int aq = (kb + ak) >> 3;
            int bq = (kb + bk) >> 3;
            #pragma unroll
            for (int mt = 0; mt < 4; mt++) {
                int r = wm * 64 + mt * 16 + ar;
                ldsm4(af[mt], s0 + SWZ(r, aq));
            }
            #pragma unroll
            for (int nt = 0; nt < 2; nt++) {
                int r = wn * 32 + nt * 16 + br;
                ldsm4(bf[nt], s0 + W_ABYTES + SWZ(r, bq));
            }
            #pragma unroll
            for (int mt = 0; mt < 4; mt++)
                #pragma unroll
                for (int n8 = 0; n8 < 4; n8++)
                    mma16816(acc[mt][n8], af[mt], &bf[n8 >> 1][(n8 & 1) * 2]);
        }
    }

    // ---- epilogue ----
    int rb = lane >> 2;
    int cb = (lane & 3) * 2;
    #pragma unroll
    for (int mt = 0; mt < 4; mt++) {
        #pragma unroll
        for (int n8 = 0; n8 < 4; n8++) {
            long col = n0 + wn * 32 + n8 * 8 + cb;
            float bv0 = 0.f, bv1 = 0.f;
            if (BIAS) { bv0 = bias[col]; bv1 = bias[col + 1]; }
            #pragma unroll
            for (int h = 0; h < 2; h++) {
                long row = m0 + wm * 64 + mt * 16 + rb + h * 8;
                *reinterpret_cast<float2*>(Cf + row * (long)N + col) =
                    make_float2(acc[mt][n8][h * 2 + 0] + bv0,
                                acc[mt][n8][h * 2 + 1] + bv1);
            }
        }
    }
}

// ---------------------------------------------------------------------------
// Launch
// ---------------------------------------------------------------------------
extern "C" void kernel_launch(void* const* d_in, const int* in_sizes, int n_in,
                              void* d_out, int out_size) {
    const int*   ids = (const int*)  d_in[0];
    const float* emb = (const float*)d_in[1];
    const float* W1  = (const float*)d_in[2];
    const float* b1  = (const float*)d_in[3];
    const float* W2  = (const float*)d_in[4];
    const float* b2  = (const float*)d_in[5];
    float* out = (float*)d_out;

    float *x, *scores;
    __half *xhi, *xlo, *xThi, *xTlo, *whi, *wlo, *athi, *atlo, *hdhi, *w1t, *w2t;
    cudaGetSymbolAddress((void**)&x,      g_x);
    cudaGetSymbolAddress((void**)&scores, g_scores);
    cudaGetSymbolAddress((void**)&xhi,    g_xhi);
    cudaGetSymbolAddress((void**)&xlo,    g_xlo);
    cudaGetSymbolAddress((void**)&xThi,   g_xThi);
    cudaGetSymbolAddress((void**)&xTlo,   g_xTlo);
    cudaGetSymbolAddress((void**)&whi,    g_whi);
    cudaGetSymbolAddress((void**)&wlo,    g_wlo);
    cudaGetSymbolAddress((void**)&athi,   g_atthi);
    cudaGetSymbolAddress((void**)&atlo,   g_attlo);
    cudaGetSymbolAddress((void**)&hdhi,   g_hidhi);
    cudaGetSymbolAddress((void**)&w1t,    g_W1t);
    cudaGetSymbolAddress((void**)&w2t,    g_W2t);

    const int SM3 = 4 * NSTAGE * TILE_BYTES;  // 196608
    const int SM2 = 3 * NSTAGE * TILE_BYTES;  // 147456
    const int SMW = WNS * W_STAGE;            // 196608
    cudaFuncSetAttribute(hgemm<3, 0, false, false>, cudaFuncAttributeMaxDynamicSharedMemorySize, SM3);
    cudaFuncSetAttribute(hgemm<3, 2, false, false>, cudaFuncAttributeMaxDynamicSharedMemorySize, SM3);
    cudaFuncSetAttribute(hgemm<2, 1, true,  true >, cudaFuncAttributeMaxDynamicSharedMemorySize, SM2);
    cudaFuncSetAttribute(hgemm_ffn2<true>, cudaFuncAttributeMaxDynamicSharedMemorySize, SMW);

    // 0) embedding -> x fp32, x hi/lo fp16
    embed_kernel<<<BATCH * SEQ, 256>>>(ids, emb, x, xhi, xlo);

    // 1) xT hi/lo ([S,E] -> [E,S] per batch)
    {
        dim3 grid(EMBED / 32, SEQ / 32, BATCH);
        transpose_split_kernel<<<grid, dim3(32, 8)>>>(x, xThi, xTlo, SEQ, EMBED,
                                                      (long)SEQ * EMBED, (long)EMBED * SEQ);
    }
    // 2) W1t + W2t single fp16 (combined launch)
    {
        dim3 grid(VOCAB / 32, HID / 32, 2);
        transpose_weights_kernel<<<grid, dim3(32, 8)>>>(W1, W2, w1t, w2t);
    }

    // 3) scores = x @ x^T   (3-term, fp32 out)  M=N=2048 K=1024
    {
        dim3 grid((SEQ / BMT) * (SEQ / BNT), 1, BATCH);
        hgemm<3, 0, false, false><<<grid, 256, SM3>>>(
            xhi, xlo, xhi, xlo, nullptr, scores, nullptr, nullptr,
            SEQ, SEQ, EMBED, (long)SEQ * EMBED, (long)SEQ * EMBED, (long)SEQ * SEQ,
            SEQ / BMT);
    }

    // 4) softmax -> w hi/lo
    softmax_kernel<<<BATCH * SEQ, 256>>>(scores, whi, wlo);

    // 5) attended = w @ x   (3-term, fp16 hi/lo out)  M=2048 N=1024 K=2048
    {
        dim3 grid((SEQ / BMT) * (EMBED / BNT), 1, BATCH);
        hgemm<3, 2, false, false><<<grid, 256, SM3>>>(
            whi, wlo, xThi, xTlo, nullptr, nullptr, athi, atlo,
            SEQ, EMBED, SEQ, (long)SEQ * SEQ, (long)EMBED * SEQ, (long)SEQ * EMBED,
            SEQ / BMT);
    }

    // 6) hidden = relu(att @ W1 + b1)  (2-term A-split, fp16 hi out)  M=8192 N=4096 K=1024
    {
        dim3 grid(((BATCH * SEQ) / BMT) * (HID / BNT), 1, 1);
        hgemm<2, 1, true, true><<<grid, 256, SM2>>>(
            athi, atlo, w1t, nullptr, b1, nullptr, hdhi, nullptr,
            BATCH * SEQ, HID, EMBED, 0, 0, 0,
            (BATCH * SEQ) / BMT);
    }

    // 7) logits = hidden @ W2 + b2  (1-term, 512-thread, fp32 out)  M=8192 N=32000 K=4096
    {
        dim3 grid(((BATCH * SEQ) / 128) * (VOCAB / 256), 1, 1);
        hgemm_ffn2<true><<<grid, 512, SMW>>>(
            hdhi, w2t, b2, out, BATCH * SEQ, VOCAB, HID, (BATCH * SEQ) / 128);
    }
}

// round 9
// speedup vs baseline: 1.6113x; 1.6113x over previous
#include <cuda_runtime.h>
#include <cuda_fp16.h>
#include <cstdint>

// Problem dims
#define BATCH 4
#define SEQ   2048
#define EMBED 1024
#define HID   4096
#define VOCAB 32000

// ---------------------------------------------------------------------------
// PTX helpers (plain sm_103-legal: cp.async / ldmatrix / mma.sync only)
// ---------------------------------------------------------------------------
__device__ __forceinline__ uint32_t smem_u32(const void* p) {
    uint32_t a;
    asm("{ .reg .u64 t; cvta.to.shared.u64 t, %1; cvt.u32.u64 %0, t; }" : "=r"(a) : "l"(p));
    return a;
}
#define CP_ASYNC16(s, g) \
    asm volatile("cp.async.cg.shared.global [%0], [%1], 16;\n" :: "r"(s), "l"(g))
#define CP_COMMIT() asm volatile("cp.async.commit_group;\n" ::: "memory")
#define CP_WAIT1()  asm volatile("cp.async.wait_group 1;\n" ::: "memory")
#define CP_WAIT2()  asm volatile("cp.async.wait_group 2;\n" ::: "memory")

__device__ __forceinline__ void ldsm4(uint32_t* r, uint32_t a) {
    asm volatile("ldmatrix.sync.aligned.m8n8.x4.shared.b16 {%0,%1,%2,%3}, [%4];"
        : "=r"(r[0]), "=r"(r[1]), "=r"(r[2]), "=r"(r[3]) : "r"(a));
}
__device__ __forceinline__ void mma16816(float* c, const uint32_t* a, const uint32_t* b) {
    asm volatile(
        "mma.sync.aligned.m16n8k16.row.col.f32.f16.f16.f32 "
        "{%0,%1,%2,%3}, {%4,%5,%6,%7}, {%8,%9}, {%0,%1,%2,%3};"
        : "+f"(c[0]), "+f"(c[1]), "+f"(c[2]), "+f"(c[3])
        : "r"(a[0]), "r"(a[1]), "r"(a[2]), "r"(a[3]), "r"(b[0]), "r"(b[1]));
}

// 128B-row SW128 swizzle: row r, 16B-chunk q (0..7) -> byte offset in tile
#define SWZ(r, q) ((uint32_t)((r) * 128 + ((((q) ^ ((r) & 7))) << 4)))

// fp16 hi/lo split (hi+lo covers ~22 mantissa bits of the fp32 value)
__device__ __forceinline__ void hsplit(float v, __half& h, __half& l) {
    h = __float2half_rn(v);
    l = __float2half_rn(v - __half2float(h));
}

// ---------------------------------------------------------------------------
// Scratch (device globals)
// ---------------------------------------------------------------------------
__device__ float  g_x     [BATCH * SEQ * EMBED];
__device__ __half g_xhi   [BATCH * SEQ * EMBED];
__device__ __half g_xlo   [BATCH * SEQ * EMBED];
__device__ __half g_xThi  [BATCH * EMBED * SEQ];
__device__ __half g_xTlo  [BATCH * EMBED * SEQ];
__device__ float  g_scores[BATCH * SEQ * SEQ];
__device__ __half g_whi   [BATCH * SEQ * SEQ];
__device__ __half g_wlo   [BATCH * SEQ * SEQ];
__device__ __half g_atthi [BATCH * SEQ * EMBED];
__device__ __half g_attlo [BATCH * SEQ * EMBED];
__device__ __half g_hidhi [BATCH * SEQ * HID];
__device__ __half g_W1t   [HID * EMBED];
__device__ __half g_W2t   [(size_t)VOCAB * HID];

// ---------------------------------------------------------------------------
// Embedding gather: x fp32 + fp16 hi/lo
// ---------------------------------------------------------------------------
__global__ void embed_kernel(const int* __restrict__ ids, const float* __restrict__ emb,
                             float* __restrict__ x,
                             __half* __restrict__ xhi, __half* __restrict__ xlo) {
    int row = blockIdx.x;
    int id  = ids[row];
    int t = threadIdx.x;
    float4 v = reinterpret_cast<const float4*>(emb + (long)id * EMBED)[t];
    reinterpret_cast<float4*>(x + (long)row * EMBED)[t] = v;
    __half h0, l0, h1, l1, h2, l2, h3, l3;
    hsplit(v.x, h0, l0); hsplit(v.y, h1, l1); hsplit(v.z, h2, l2); hsplit(v.w, h3, l3);
    __half2* dh = reinterpret_cast<__half2*>(xhi + (long)row * EMBED) + t * 2;
    __half2* dl = reinterpret_cast<__half2*>(xlo + (long)row * EMBED) + t * 2;
    dh[0] = __halves2half2(h0, h1); dh[1] = __halves2half2(h2, h3);
    dl[0] = __halves2half2(l0, l1); dl[1] = __halves2half2(l2, l3);
}

// ---------------------------------------------------------------------------
// Transpose fp32 [R,C] -> fp16 [C,R] hi/lo, batched via z (for xT)
// ---------------------------------------------------------------------------
__global__ void transpose_split_kernel(const float* __restrict__ in,
                                       __half* __restrict__ ohi, __half* __restrict__ olo,
                                       int R, int C, long sIn, long sOut) {
    __shared__ float t[32][33];
    long z = blockIdx.z;
    in  += z * sIn;
    ohi += z * sOut; olo += z * sOut;
    int c0 = blockIdx.x * 32, r0 = blockIdx.y * 32;
    int tx = threadIdx.x, ty = threadIdx.y;
    #pragma unroll
    for (int i = 0; i < 32; i += 8)
        t[ty + i][tx] = in[(long)(r0 + ty + i) * C + c0 + tx];
    __syncthreads();
    #pragma unroll
    for (int i = 0; i < 32; i += 8) {
        float v = t[tx][ty + i];
        __half h, l; hsplit(v, h, l);
        long o = (long)(c0 + ty + i) * R + r0 + tx;
        ohi[o] = h; olo[o] = l;
    }
}

// ---------------------------------------------------------------------------
// Combined weight transpose: z=0 -> W1 [E,H] -> w1t [H,E]
//                            z=1 -> W2 [H,V] -> w2t [V,H]
// ---------------------------------------------------------------------------
__global__ void transpose_weights_kernel(const float* __restrict__ W1,
                                         const float* __restrict__ W2,
                                         __half* __restrict__ w1t,
                                         __half* __restrict__ w2t) {
    __shared__ float t[32][33];
    const float* in; __half* outp; int R, C;
    if (blockIdx.z == 0) {
        if (blockIdx.x >= HID / 32 || blockIdx.y >= EMBED / 32) return;
        in = W1; outp = w1t; R = EMBED; C = HID;
    } else {
        in = W2; outp = w2t; R = HID; C = VOCAB;
    }
    int c0 = blockIdx.x * 32, r0 = blockIdx.y * 32;
    int tx = threadIdx.x, ty = threadIdx.y;
    #pragma unroll
    for (int i = 0; i < 32; i += 8)
        t[ty + i][tx] = in[(long)(r0 + ty + i) * C + c0 + tx];
    __syncthreads();
    #pragma unroll
    for (int i = 0; i < 32; i += 8) {
        long o = (long)(c0 + ty + i) * R + r0 + tx;
        outp[o] = __float2half_rn(t[tx][ty + i]);
    }
}

// ---------------------------------------------------------------------------
// Softmax rows (fp32 in) -> fp16 hi/lo weights
// ---------------------------------------------------------------------------
__global__ __launch_bounds__(256)
void softmax_kernel(const float* __restrict__ scores,
                    __half* __restrict__ whi, __half* __restrict__ wlo) {
    __shared__ float red[256];
    const float* row = scores + (long)blockIdx.x * SEQ;
    __half* oh = whi + (long)blockIdx.x * SEQ;
    __half* ol = wlo + (long)blockIdx.x * SEQ;
    const int tid = threadIdx.x;

    float v[8];
    float lmax = -3.402823466e+38f;
    #pragma unroll
    for (int i = 0; i < 8; i++) { v[i] = row[tid + i * 256]; lmax = fmaxf(lmax, v[i]); }
    red[tid] = lmax; __syncthreads();
    #pragma unroll
    for (int s = 128; s > 0; s >>= 1) { if (tid < s) red[tid] = fmaxf(red[tid], red[tid + s]); __syncthreads(); }
    float m = red[0]; __syncthreads();

    float lsum = 0.f;
    #pragma unroll
    for (int i = 0; i < 8; i++) { v[i] = __expf(v[i] - m); lsum += v[i]; }
    red[tid] = lsum; __syncthreads();
    #pragma unroll
    for (int s = 128; s > 0; s >>= 1) { if (tid < s) red[tid] += red[tid + s]; __syncthreads(); }
    float inv = 1.f / red[0];
    #pragma unroll
    for (int i = 0; i < 8; i++) {
        float w = v[i] * inv;
        __half h, l; hsplit(w, h, l);
        oh[tid + i * 256] = h; ol[tid + i * 256] = l;
    }
}

// ---------------------------------------------------------------------------
// HMMA split-fp16 GEMM (attention + FFN1):  C[M,N] = A[M,K] * B[N,K]^T
// MODE=2: A0*B0 + A1*B0.  MODE=3: + A0*B1.
// OUT=0: fp32 (+bias,+relu)   OUT=1: fp16 hi only   OUT=2: fp16 hi/lo
// CTA 128x128, BK=64 (SW128 rows), 8 warps, 3 stages. (R6 configuration.)
// ---------------------------------------------------------------------------
#define BMT 128
#define BNT 128
#define BKT 64
#define NSTAGE 3
#define TILE_BYTES 16384    // 128 rows x 128 B

template<int TPS>
__device__ __forceinline__ void load_chunk(uint32_t sbase, int st,
    const __half* __restrict__ gA0, const __half* __restrict__ gA1,
    const __half* __restrict__ gB0, const __half* __restrict__ gB1,
    int K, int k0, int tid)
{
    uint32_t s0 = sbase + (uint32_t)(st * TPS * TILE_BYTES);
    #pragma unroll
    for (int it = 0; it < 4; it++) {
        int idx = tid + it * 256;
        int r = idx >> 3, c = idx & 7;
        uint32_t so = SWZ(r, c);
        long go = (long)r * K + k0 + c * 8;
        CP_ASYNC16(s0 + 0 * TILE_BYTES + so, gA0 + go);
        CP_ASYNC16(s0 + 1 * TILE_BYTES + so, gA1 + go);
        CP_ASYNC16(s0 + 2 * TILE_BYTES + so, gB0 + go);
        if (TPS == 4) CP_ASYNC16(s0 + 3 * TILE_BYTES + so, gB1 + go);
    }
}

template<int MODE, int OUT, bool BIAS, bool RELU>
__global__ __launch_bounds__(256)
void hgemm(const __half* __restrict__ A0, const __half* __restrict__ A1,
           const __half* __restrict__ B0, const __half* __restrict__ B1,
           const float* __restrict__ bias,
           float* __restrict__ Cf, __half* __restrict__ Chi, __half* __restrict__ Clo,
           int M, int N, int K, long sA, long sB, long sC, int ntm)
{
    extern __shared__ char smem[];
    const uint32_t sbase = smem_u32(smem);
    const int tid  = threadIdx.x;
    const int wid  = tid >> 5, lane = tid & 31;
    const int wm   = wid & 1,  wn   = wid >> 1;
    constexpr int TPS = (MODE == 3) ? 4 : 3;

    int pm = blockIdx.x % ntm, pn = blockIdx.x / ntm;
    long m0 = (long)pm * BMT, n0 = (long)pn * BNT;
    long zb = blockIdx.z;
    const __half* gA0 = A0 + zb * sA + m0 * K;
    const __half* gA1 = A1 + zb * sA + m0 * K;
    const __half* gB0 = B0 + zb * sB + n0 * K;
    const __half* gB1 = (MODE == 3) ? (B1 + zb * sB + n0 * K) : gB0;

    float acc[4][4][4];
    #pragma unroll
    for (int i = 0; i < 4; i++)
        #pragma unroll
        for (int j = 0; j < 4; j++)
            #pragma unroll
            for (int k = 0; k < 4; k++) acc[i][j][k] = 0.f;

    const int ar = lane & 15;
    const int ak = (lane >> 4) << 3;
    const int br = ((lane >> 4) << 3) + (lane & 7);
    const int bk = ((lane >> 3) & 1) << 3;

    load_chunk<TPS>(sbase, 0, gA0, gA1, gB0, gB1, K, 0, tid);   CP_COMMIT();
    load_chunk<TPS>(sbase, 1, gA0, gA1, gB0, gB1, K, BKT, tid); CP_COMMIT();

    const int nc = K / BKT;
    for (int c = 0; c < nc; c++) {
        CP_WAIT1();
        __syncthreads();
        if (c + 2 < nc)
            load_chunk<TPS>(sbase, (c + 2) % NSTAGE, gA0, gA1, gB0, gB1, K, (c + 2) * BKT, tid);
        CP_COMMIT();

        uint32_t s0 = sbase + (uint32_t)((c % NSTAGE) * TPS * TILE_BYTES);
        #pragma unroll
        for (int kb = 0; kb < BKT; kb += 16) {
            uint32_t a0f[4][4], a1f[4][4], b0f[2][4], b1f[2][4];
            int aq = (kb + ak) >> 3;
            int bq = (kb + bk) >> 3;
            #pragma unroll
            for (int mt = 0; mt < 4; mt++) {
                int r = wm * 64 + mt * 16 + ar;
                uint32_t ad = s0 + SWZ(r, aq);
                ldsm4(a0f[mt], ad);
                ldsm4(a1f[mt], ad + TILE_BYTES);
            }
            #pragma unroll
            for (int nt = 0; nt < 2; nt++) {
                int r = wn * 32 + nt * 16 + br;
                uint32_t bd = s0 + 2 * TILE_BYTES + SWZ(r, bq);
                ldsm4(b0f[nt], bd);
                if (MODE == 3) ldsm4(b1f[nt], bd + TILE_BYTES);
            }
            #pragma unroll
            for (int mt = 0; mt < 4; mt++)
                #pragma unroll
                for (int n8 = 0; n8 < 4; n8++) {
                    const uint32_t* b = &b0f[n8 >> 1][(n8 & 1) * 2];
                    mma16816(acc[mt][n8], a0f[mt], b);
                    mma16816(acc[mt][n8], a1f[mt], b);
                    if (MODE == 3)
                        mma16816(acc[mt][n8], a0f[mt], &b1f[n8 >> 1][(n8 & 1) * 2]);
                }
        }
    }

    // ---- epilogue ----
    long zC = zb * sC;
    int rb = lane >> 2;
    int cb = (lane & 3) * 2;
    #pragma unroll
    for (int mt = 0; mt < 4; mt++) {
        #pragma unroll
        for (int n8 = 0; n8 < 4; n8++) {
            long col = n0 + wn * 32 + n8 * 8 + cb;
            float bv0 = 0.f, bv1 = 0.f;
            if (BIAS) { bv0 = bias[col]; bv1 = bias[col + 1]; }
            #pragma unroll
            for (int h = 0; h < 2; h++) {
                long row = m0 + wm * 64 + mt * 16 + rb + h * 8;
                float v0 = acc[mt][n8][h * 2 + 0] + bv0;
                float v1 = acc[mt][n8][h * 2 + 1] + bv1;
                if (RELU) { v0 = fmaxf(v0, 0.f); v1 = fmaxf(v1, 0.f); }
                long o = row * (long)N + col;
                if (OUT == 0) {
                    *reinterpret_cast<float2*>(Cf + zC + o) = make_float2(v0, v1);
                } else if (OUT == 1) {
                    *reinterpret_cast<__half2*>(Chi + zC + o) =
                        __halves2half2(__float2half_rn(v0), __float2half_rn(v1));
                } else {
                    __half h0, l0, h1, l1;
                    hsplit(v0, h0, l0); hsplit(v1, h1, l1);
                    *reinterpret_cast<__half2*>(Chi + zC + o) = __halves2half2(h0, h1);
                    *reinterpret_cast<__half2*>(Clo + zC + o) = __halves2half2(l0, l1);
                }
            }
        }
    }
}

// ---------------------------------------------------------------------------
// FFN2 GEMM: 2 CTAs/SM.  CTA 128x128, BK=64, 8 warps (64x32 warp tile),
// 3 stages (96 KB smem/CTA -> two co-resident CTAs), 256 thr,
// __launch_bounds__(256,2): ~115 regs/thread, no spill.
// 4 independent eligible warps per SMSP hide ldsm/barrier latency.
// ---------------------------------------------------------------------------
#define F2_STAGE (2 * TILE_BYTES)      // A tile + B tile = 32 KB
#define F2_SMEM  (NSTAGE * F2_STAGE)   // 98304

__device__ __forceinline__ void load_chunk_f2(uint32_t sbase, int st,
    const __half* __restrict__ gA, const __half* __restrict__ gB,
    int K, int k0, int tid)
{
    uint32_t s0 = sbase + (uint32_t)(st * F2_STAGE);
    #pragma unroll
    for (int it = 0; it < 4; it++) {
        int idx = tid + it * 256;
        int r = idx >> 3, c = idx & 7;
        uint32_t so = SWZ(r, c);
        long go = (long)r * K + k0 + c * 8;
        CP_ASYNC16(s0 + so, gA + go);
        CP_ASYNC16(s0 + TILE_BYTES + so, gB + go);
    }
}

template<bool BIAS>
__global__ __launch_bounds__(256, 2)
void hgemm_ffn2(const __half* __restrict__ A0, const __half* __restrict__ B0,
                const float* __restrict__ bias, float* __restrict__ Cf,
                int M, int N, int K, int ntm)
{
    extern __shared__ char smem[];
    const uint32_t sbase = smem_u32(smem);
    const int tid  = threadIdx.x;
    const int wid  = tid >> 5, lane = tid & 31;
    const int wm   = wid & 1,  wn   = wid >> 1;

    int pm = blockIdx.x % ntm, pn = blockIdx.x / ntm;
    long m0 = (long)pm * 128, n0 = (long)pn * 128;
    const __half* gA = A0 + m0 * K;
    const __half* gB = B0 + n0 * K;

    float acc[4][4][4];
    #pragma unroll
    for (int i = 0; i < 4; i++)
        #pragma unroll
        for (int j = 0; j < 4; j++)
            #pragma unroll
            for (int k = 0; k < 4; k++) acc[i][j][k] = 0.f;

    const int ar = lane & 15;
    const int ak = (lane >> 4) << 3;
    const int br = ((lane >> 4) << 3) + (lane & 7);
    const int bk = ((lane >> 3) & 1) << 3;

    load_chunk_f2(sbase, 0, gA, gB, K, 0, tid);    CP_COMMIT();
    load_chunk_f2(sbase, 1, gA, gB, K, BKT, tid);  CP_COMMIT();

    const int nc = K / BKT;
    for (int c = 0; c < nc; c++) {
        CP_WAIT1();
        __syncthreads();
        if (c + 2 < nc)
            load_chunk_f2(sbase, (c + 2) % NSTAGE, gA, gB, K, (c + 2) * BKT, tid);
        CP_COMMIT();

        uint32_t s0 = sbase + (uint32_t)((c % NSTAGE) * F2_STAGE);
        #pragma unroll
        for (int kb = 0; kb < BKT; kb += 16) {
            uint32_t af[4][4], bf[2][4];
            int aq = (kb + ak) >> 3;
            int bq = (kb + bk) >> 3;
            #pragma unroll
            for (int mt = 0; mt < 4; mt++) {
                int r = wm * 64 + mt * 16 + ar;
                ldsm4(af[mt], s0 + SWZ(r, aq));
            }
            #pragma unroll
            for (int nt = 0; nt < 2; nt++) {
                int r = wn * 32 + nt * 16 + br;
                ldsm4(bf[nt], s0 + TILE_BYTES + SWZ(r, bq));
            }
            #pragma unroll
            for (int mt = 0; mt < 4; mt++)
                #pragma unroll
                for (int n8 = 0; n8 < 4; n8++)
                    mma16816(acc[mt][n8], af[mt], &bf[n8 >> 1][(n8 & 1) * 2]);
        }
    }

    // ---- epilogue ----
    int rb = lane >> 2;
    int cb = (lane & 3) * 2;
    #pragma unroll
    for (int mt = 0; mt < 4; mt++) {
        #pragma unroll
        for (int n8 = 0; n8 < 4; n8++) {
            long col = n0 + wn * 32 + n8 * 8 + cb;
            float bv0 = 0.f, bv1 = 0.f;
            if (BIAS) { bv0 = bias[col]; bv1 = bias[col + 1]; }
            #pragma unroll
            for (int h = 0; h < 2; h++) {
                long row = m0 + wm * 64 + mt * 16 + rb + h * 8;
                *reinterpret_cast<float2*>(Cf + row * (long)N + col) =
                    make_float2(acc[mt][n8][h * 2 + 0] + bv0,
                                acc[mt][n8][h * 2 + 1] + bv1);
            }
        }
    }
}

// ---------------------------------------------------------------------------
// Launch
// ---------------------------------------------------------------------------
extern "C" void kernel_launch(void* const* d_in, const int* in_sizes, int n_in,
                              void* d_out, int out_size) {
    const int*   ids = (const int*)  d_in[0];
    const float* emb = (const float*)d_in[1];
    const float* W1  = (const float*)d_in[2];
    const float* b1  = (const float*)d_in[3];
    const float* W2  = (const float*)d_in[4];
    const float* b2  = (const float*)d_in[5];
    float* out = (float*)d_out;

    float *x, *scores;
    __half *xhi, *xlo, *xThi, *xTlo, *whi, *wlo, *athi, *atlo, *hdhi, *w1t, *w2t;
    cudaGetSymbolAddress((void**)&x,      g_x);
    cudaGetSymbolAddress((void**)&scores, g_scores);
    cudaGetSymbolAddress((void**)&xhi,    g_xhi);
    cudaGetSymbolAddress((void**)&xlo,    g_xlo);
    cudaGetSymbolAddress((void**)&xThi,   g_xThi);
    cudaGetSymbolAddress((void**)&xTlo,   g_xTlo);
    cudaGetSymbolAddress((void**)&whi,    g_whi);
    cudaGetSymbolAddress((void**)&wlo,    g_wlo);
    cudaGetSymbolAddress((void**)&athi,   g_atthi);
    cudaGetSymbolAddress((void**)&atlo,   g_attlo);
    cudaGetSymbolAddress((void**)&hdhi,   g_hidhi);
    cudaGetSymbolAddress((void**)&w1t,    g_W1t);
    cudaGetSymbolAddress((void**)&w2t,    g_W2t);

    const int SM3 = 4 * NSTAGE * TILE_BYTES;  // 196608
    const int SM2 = 3 * NSTAGE * TILE_BYTES;  // 147456
    cudaFuncSetAttribute(hgemm<3, 0, false, false>, cudaFuncAttributeMaxDynamicSharedMemorySize, SM3);
    cudaFuncSetAttribute(hgemm<3, 2, false, false>, cudaFuncAttributeMaxDynamicSharedMemorySize, SM3);
    cudaFuncSetAttribute(hgemm<2, 1, true,  true >, cudaFuncAttributeMaxDynamicSharedMemorySize, SM2);
    cudaFuncSetAttribute(hgemm_ffn2<true>, cudaFuncAttributeMaxDynamicSharedMemorySize, F2_SMEM);

    // 0) embedding -> x fp32, x hi/lo fp16
    embed_kernel<<<BATCH * SEQ, 256>>>(ids, emb, x, xhi, xlo);

    // 1) xT hi/lo ([S,E] -> [E,S] per batch)
    {
        dim3 grid(EMBED / 32, SEQ / 32, BATCH);
        transpose_split_kernel<<<grid, dim3(32, 8)>>>(x, xThi, xTlo, SEQ, EMBED,
                                                      (long)SEQ * EMBED, (long)EMBED * SEQ);
    }
    // 2) W1t + W2t single fp16 (combined launch)
    {
        dim3 grid(VOCAB / 32, HID / 32, 2);
        transpose_weights_kernel<<<grid, dim3(32, 8)>>>(W1, W2, w1t, w2t);
    }

    // 3) scores = x @ x^T   (3-term, fp32 out)  M=N=2048 K=1024
    {
        dim3 grid((SEQ / BMT) * (SEQ / BNT), 1, BATCH);
        hgemm<3, 0, false, false><<<grid, 256, SM3>>>(
            xhi, xlo, xhi, xlo, nullptr, scores, nullptr, nullptr,
            SEQ, SEQ, EMBED, (long)SEQ * EMBED, (long)SEQ * EMBED, (long)SEQ * SEQ,
            SEQ / BMT);
    }

    // 4) softmax -> w hi/lo
    softmax_kernel<<<BATCH * SEQ, 256>>>(scores, whi, wlo);

    // 5) attended = w @ x   (3-term, fp16 hi/lo out)  M=2048 N=1024 K=2048
    {
        dim3 grid((SEQ / BMT) * (EMBED / BNT), 1, BATCH);
        hgemm<3, 2, false, false><<<grid, 256, SM3>>>(
            whi, wlo, xThi, xTlo, nullptr, nullptr, athi, atlo,
            SEQ, EMBED, SEQ, (long)SEQ * SEQ, (long)EMBED * SEQ, (long)SEQ * EMBED,
            SEQ / BMT);
    }

    // 6) hidden = relu(att @ W1 + b1)  (2-term A-split, fp16 hi out)  M=8192 N=4096 K=1024
    {
        dim3 grid(((BATCH * SEQ) / BMT) * (HID / BNT), 1, 1);
        hgemm<2, 1, true, true><<<grid, 256, SM2>>>(
            athi, atlo, w1t, nullptr, b1, nullptr, hdhi, nullptr,
            BATCH * SEQ, HID, EMBED, 0, 0, 0,
            (BATCH * SEQ) / BMT);
    }

    // 7) logits = hidden @ W2 + b2  (1-term, 2 CTA/SM, fp32 out)  M=8192 N=32000 K=4096
    {
        dim3 grid(((BATCH * SEQ) / 128) * (VOCAB / 128), 1, 1);
        hgemm_ffn2<true><<<grid, 256, F2_SMEM>>>(
            hdhi, w2t, b2, out, BATCH * SEQ, VOCAB, HID, (BATCH * SEQ) / 128);
    }
}

// round 10
// speedup vs baseline: 1.6600x; 1.0302x over previous
#include <cuda_runtime.h>
#include <cuda_fp16.h>
#include <cstdint>

// Problem dims
#define BATCH 4
#define SEQ   2048
#define EMBED 1024
#define HID   4096
#define VOCAB 32000

// ---------------------------------------------------------------------------
// PTX helpers (plain sm_103-legal: cp.async / ldmatrix / mma.sync only)
// ---------------------------------------------------------------------------
__device__ __forceinline__ uint32_t smem_u32(const void* p) {
    uint32_t a;
    asm("{ .reg .u64 t; cvta.to.shared.u64 t, %1; cvt.u32.u64 %0, t; }" : "=r"(a) : "l"(p));
    return a;
}
#define CP_ASYNC16(s, g) \
    asm volatile("cp.async.cg.shared.global [%0], [%1], 16;\n" :: "r"(s), "l"(g))
#define CP_COMMIT() asm volatile("cp.async.commit_group;\n" ::: "memory")
#define CP_WAIT1()  asm volatile("cp.async.wait_group 1;\n" ::: "memory")

__device__ __forceinline__ void ldsm4(uint32_t* r, uint32_t a) {
    asm volatile("ldmatrix.sync.aligned.m8n8.x4.shared.b16 {%0,%1,%2,%3}, [%4];"
        : "=r"(r[0]), "=r"(r[1]), "=r"(r[2]), "=r"(r[3]) : "r"(a));
}
__device__ __forceinline__ void mma16816(float* c, const uint32_t* a, const uint32_t* b) {
    asm volatile(
        "mma.sync.aligned.m16n8k16.row.col.f32.f16.f16.f32 "
        "{%0,%1,%2,%3}, {%4,%5,%6,%7}, {%8,%9}, {%0,%1,%2,%3};"
        : "+f"(c[0]), "+f"(c[1]), "+f"(c[2]), "+f"(c[3])
        : "r"(a[0]), "r"(a[1]), "r"(a[2]), "r"(a[3]), "r"(b[0]), "r"(b[1]));
}

// 128B-row SW128 swizzle: row r, 16B-chunk q (0..7) -> byte offset in tile
#define SWZ(r, q) ((uint32_t)((r) * 128 + ((((q) ^ ((r) & 7))) << 4)))

// fp16 hi/lo split (hi+lo covers ~22 mantissa bits of the fp32 value)
__device__ __forceinline__ void hsplit(float v, __half& h, __half& l) {
    h = __float2half_rn(v);
    l = __float2half_rn(v - __half2float(h));
}

// ---------------------------------------------------------------------------
// Scratch (device globals)
// ---------------------------------------------------------------------------
__device__ float  g_x     [BATCH * SEQ * EMBED];
__device__ __half g_xhi   [BATCH * SEQ * EMBED];
__device__ __half g_xlo   [BATCH * SEQ * EMBED];
__device__ __half g_xThi  [BATCH * EMBED * SEQ];
__device__ float  g_scores[BATCH * SEQ * SEQ];
__device__ __half g_whi   [BATCH * SEQ * SEQ];
__device__ __half g_wlo   [BATCH * SEQ * SEQ];
__device__ __half g_atthi [BATCH * SEQ * EMBED];
__device__ __half g_attlo [BATCH * SEQ * EMBED];
__device__ __half g_hidhi [BATCH * SEQ * HID];
__device__ __half g_W1t   [HID * EMBED];
__device__ __half g_W2t   [(size_t)VOCAB * HID];

// ---------------------------------------------------------------------------
// Embedding gather: x fp32 + fp16 hi/lo
// ---------------------------------------------------------------------------
__global__ void embed_kernel(const int* __restrict__ ids, const float* __restrict__ emb,
                             float* __restrict__ x,
                             __half* __restrict__ xhi, __half* __restrict__ xlo) {
    int row = blockIdx.x;
    int id  = ids[row];
    int t = threadIdx.x;
    float4 v = reinterpret_cast<const float4*>(emb + (long)id * EMBED)[t];
    reinterpret_cast<float4*>(x + (long)row * EMBED)[t] = v;
    __half h0, l0, h1, l1, h2, l2, h3, l3;
    hsplit(v.x, h0, l0); hsplit(v.y, h1, l1); hsplit(v.z, h2, l2); hsplit(v.w, h3, l3);
    __half2* dh = reinterpret_cast<__half2*>(xhi + (long)row * EMBED) + t * 2;
    __half2* dl = reinterpret_cast<__half2*>(xlo + (long)row * EMBED) + t * 2;
    dh[0] = __halves2half2(h0, h1); dh[1] = __halves2half2(h2, h3);
    dl[0] = __halves2half2(l0, l1); dl[1] = __halves2half2(l2, l3);
}

// ---------------------------------------------------------------------------
// Transpose fp32 [R,C] -> single fp16 [C,R], batched via z (for xT)
// ---------------------------------------------------------------------------
__global__ void transpose_single_kernel(const float* __restrict__ in,
                                        __half* __restrict__ o,
                                        int R, int C, long sIn, long sOut) {
    __shared__ float t[32][33];
    long z = blockIdx.z;
    in += z * sIn;
    o  += z * sOut;
    int c0 = blockIdx.x * 32, r0 = blockIdx.y * 32;
    int tx = threadIdx.x, ty = threadIdx.y;
    #pragma unroll
    for (int i = 0; i < 32; i += 8)
        t[ty + i][tx] = in[(long)(r0 + ty + i) * C + c0 + tx];
    __syncthreads();
    #pragma unroll
    for (int i = 0; i < 32; i += 8) {
        long oo = (long)(c0 + ty + i) * R + r0 + tx;
        o[oo] = __float2half_rn(t[tx][ty + i]);
    }
}

// ---------------------------------------------------------------------------
// Combined weight transpose: z=0 -> W1 [E,H] -> w1t [H,E]
//                            z=1 -> W2 [H,V] -> w2t [V,H]
// ---------------------------------------------------------------------------
__global__ void transpose_weights_kernel(const float* __restrict__ W1,
                                         const float* __restrict__ W2,
                                         __half* __restrict__ w1t,
                                         __half* __restrict__ w2t) {
    __shared__ float t[32][33];
    const float* in; __half* outp; int R, C;
    if (blockIdx.z == 0) {
        if (blockIdx.x >= HID / 32 || blockIdx.y >= EMBED / 32) return;
        in = W1; outp = w1t; R = EMBED; C = HID;
    } else {
        in = W2; outp = w2t; R = HID; C = VOCAB;
    }
    int c0 = blockIdx.x * 32, r0 = blockIdx.y * 32;
    int tx = threadIdx.x, ty = threadIdx.y;
    #pragma unroll
    for (int i = 0; i < 32; i += 8)
        t[ty + i][tx] = in[(long)(r0 + ty + i) * C + c0 + tx];
    __syncthreads();
    #pragma unroll
    for (int i = 0; i < 32; i += 8) {
        long o = (long)(c0 + ty + i) * R + r0 + tx;
        outp[o] = __float2half_rn(t[tx][ty + i]);
    }
}

// ---------------------------------------------------------------------------
// Softmax rows (fp32 in) -> fp16 hi/lo weights
// ---------------------------------------------------------------------------
__global__ __launch_bounds__(256)
void softmax_kernel(const float* __restrict__ scores,
                    __half* __restrict__ whi, __half* __restrict__ wlo) {
    __shared__ float red[256];
    const float* row = scores + (long)blockIdx.x * SEQ;
    __half* oh = whi + (long)blockIdx.x * SEQ;
    __half* ol = wlo + (long)blockIdx.x * SEQ;
    const int tid = threadIdx.x;

    float v[8];
    float lmax = -3.402823466e+38f;
    #pragma unroll
    for (int i = 0; i < 8; i++) { v[i] = row[tid + i * 256]; lmax = fmaxf(lmax, v[i]); }
    red[tid] = lmax; __syncthreads();
    #pragma unroll
    for (int s = 128; s > 0; s >>= 1) { if (tid < s) red[tid] = fmaxf(red[tid], red[tid + s]); __syncthreads(); }
    float m = red[0]; __syncthreads();

    float lsum = 0.f;
    #pragma unroll
    for (int i = 0; i < 8; i++) { v[i] = __expf(v[i] - m); lsum += v[i]; }
    red[tid] = lsum; __syncthreads();
    #pragma unroll
    for (int s = 128; s > 0; s >>= 1) { if (tid < s) red[tid] += red[tid + s]; __syncthreads(); }
    float inv = 1.f / red[0];
    #pragma unroll
    for (int i = 0; i < 8; i++) {
        float w = v[i] * inv;
        __half h, l; hsplit(w, h, l);
        oh[tid + i * 256] = h; ol[tid + i * 256] = l;
    }
}

// ---------------------------------------------------------------------------
// HMMA split-fp16 GEMM:  C[M,N] = A[M,K] * B[N,K]^T
// MODE=2: A0*B0 + A1*B0 (3 tiles/stage).  MODE=3: + A0*B1 (4 tiles/stage).
// OUT=0: fp32 (+bias,+relu)   OUT=1: fp16 hi only   OUT=2: fp16 hi/lo
// CTA 128x128, BK=64 (SW128 rows), 8 warps.
// NST=3, MINB=1: 3-stage single-CTA pipeline (for MODE3 / scores).
// NST=2, MINB=2: 2-stage pipeline, 2 CTAs/SM (for MODE2: attended, FFN1).
// ---------------------------------------------------------------------------
#define BMT 128
#define BNT 128
#define BKT 64
#define TILE_BYTES 16384    // 128 rows x 128 B

template<int TPS>
__device__ __forceinline__ void load_chunk(uint32_t sbase, int st,
    const __half* __restrict__ gA0, const __half* __restrict__ gA1,
    const __half* __restrict__ gB0, const __half* __restrict__ gB1,
    int K, int k0, int tid)
{
    uint32_t s0 = sbase + (uint32_t)(st * TPS * TILE_BYTES);
    #pragma unroll
    for (int it = 0; it < 4; it++) {
        int idx = tid + it * 256;
        int r = idx >> 3, c = idx & 7;
        uint32_t so = SWZ(r, c);
        long go = (long)r * K + k0 + c * 8;
        CP_ASYNC16(s0 + 0 * TILE_BYTES + so, gA0 + go);
        CP_ASYNC16(s0 + 1 * TILE_BYTES + so, gA1 + go);
        CP_ASYNC16(s0 + 2 * TILE_BYTES + so, gB0 + go);
        if (TPS == 4) CP_ASYNC16(s0 + 3 * TILE_BYTES + so, gB1 + go);
    }
}

template<int MODE, int OUT, bool BIAS, bool RELU, int NST, int MINB>
__global__ __launch_bounds__(256, MINB)
void hgemm(const __half* __restrict__ A0, const __half* __restrict__ A1,
           const __half* __restrict__ B0, const __half* __restrict__ B1,
           const float* __restrict__ bias,
           float* __restrict__ Cf, __half* __restrict__ Chi, __half* __restrict__ Clo,
           int M, int N, int K, long sA, long sB, long sC, int ntm)
{
    extern __shared__ char smem[];
    const uint32_t sbase = smem_u32(smem);
    const int tid  = threadIdx.x;
    const int wid  = tid >> 5, lane = tid & 31;
    const int wm   = wid & 1,  wn   = wid >> 1;
    constexpr int TPS = (MODE == 3) ? 4 : 3;

    int pm = blockIdx.x % ntm, pn = blockIdx.x / ntm;
    long m0 = (long)pm * BMT, n0 = (long)pn * BNT;
    long zb = blockIdx.z;
    const __half* gA0 = A0 + zb * sA + m0 * K;
    const __half* gA1 = A1 + zb * sA + m0 * K;
    const __half* gB0 = B0 + zb * sB + n0 * K;
    const __half* gB1 = (MODE == 3) ? (B1 + zb * sB + n0 * K) : gB0;

    float acc[4][4][4];
    #pragma unroll
    for (int i = 0; i < 4; i++)
        #pragma unroll
        for (int j = 0; j < 4; j++)
            #pragma unroll
            for (int k = 0; k < 4; k++) acc[i][j][k] = 0.f;

    const int ar = lane & 15;
    const int ak = (lane >> 4) << 3;
    const int br = ((lane >> 4) << 3) + (lane & 7);
    const int bk = ((lane >> 3) & 1) << 3;

    const int nc = K / BKT;

    auto compute_stage = [&](uint32_t s0) {
        #pragma unroll
        for (int kb = 0; kb < BKT; kb += 16) {
            uint32_t a0f[4][4], a1f[4][4], b0f[2][4], b1f[2][4];
            int aq = (kb + ak) >> 3;
            int bq = (kb + bk) >> 3;
            #pragma unroll
            for (int mt = 0; mt < 4; mt++) {
                int r = wm * 64 + mt * 16 + ar;
                uint32_t ad = s0 + SWZ(r, aq);
                ldsm4(a0f[mt], ad);
                ldsm4(a1f[mt], ad + TILE_BYTES);
            }
            #pragma unroll
            for (int nt = 0; nt < 2; nt++) {
                int r = wn * 32 + nt * 16 + br;
                uint32_t bd = s0 + 2 * TILE_BYTES + SWZ(r, bq);
                ldsm4(b0f[nt], bd);
                if (MODE == 3) ldsm4(b1f[nt], bd + TILE_BYTES);
            }
            #pragma unroll
            for (int mt = 0; mt < 4; mt++)
                #pragma unroll
                for (int n8 = 0; n8 < 4; n8++) {
                    const uint32_t* b = &b0f[n8 >> 1][(n8 & 1) * 2];
                    mma16816(acc[mt][n8], a0f[mt], b);
                    mma16816(acc[mt][n8], a1f[mt], b);
                    if (MODE == 3)
                        mma16816(acc[mt][n8], a0f[mt], &b1f[n8 >> 1][(n8 & 1) * 2]);
                }
        }
    };

    if (NST == 3) {
        load_chunk<TPS>(sbase, 0, gA0, gA1, gB0, gB1, K, 0, tid);   CP_COMMIT();
        load_chunk<TPS>(sbase, 1, gA0, gA1, gB0, gB1, K, BKT, tid); CP_COMMIT();
        for (int c = 0; c < nc; c++) {
            CP_WAIT1();
            __syncthreads();
            if (c + 2 < nc)
                load_chunk<TPS>(sbase, (c + 2) % 3, gA0, gA1, gB0, gB1, K, (c + 2) * BKT, tid);
            CP_COMMIT();
            compute_stage(sbase + (uint32_t)((c % 3) * TPS * TILE_BYTES));
        }
    } else {
        // 2-stage: load c+1 while computing c; barrier after compute before the
        // next iteration's load overwrites buffer (c+1)&1's partner.
        load_chunk<TPS>(sbase, 0, gA0, gA1, gB0, gB1, K, 0, tid); CP_COMMIT();
        for (int c = 0; c < nc; c++) {
            if (c + 1 < nc) {
                load_chunk<TPS>(sbase, (c + 1) & 1, gA0, gA1, gB0, gB1, K, (c + 1) * BKT, tid);
            }
            CP_COMMIT();
            CP_WAIT1();
            __syncthreads();
            compute_stage(sbase + (uint32_t)((c & 1) * TPS * TILE_BYTES));
            __syncthreads();
        }
    }

    // ---- epilogue ----
    long zC = zb * sC;
    int rb = lane >> 2;
    int cb = (lane & 3) * 2;
    #pragma unroll
    for (int mt = 0; mt < 4; mt++) {
        #pragma unroll
        for (int n8 = 0; n8 < 4; n8++) {
            long col = n0 + wn * 32 + n8 * 8 + cb;
            float bv0 = 0.f, bv1 = 0.f;
            if (BIAS) { bv0 = bias[col]; bv1 = bias[col + 1]; }
            #pragma unroll
            for (int h = 0; h < 2; h++) {
                long row = m0 + wm * 64 + mt * 16 + rb + h * 8;
                float v0 = acc[mt][n8][h * 2 + 0] + bv0;
                float v1 = acc[mt][n8][h * 2 + 1] + bv1;
                if (RELU) { v0 = fmaxf(v0, 0.f); v1 = fmaxf(v1, 0.f); }
                long o = row * (long)N + col;
                if (OUT == 0) {
                    *reinterpret_cast<float2*>(Cf + zC + o) = make_float2(v0, v1);
                } else if (OUT == 1) {
                    *reinterpret_cast<__half2*>(Chi + zC + o) =
                        __halves2half2(__float2half_rn(v0), __float2half_rn(v1));
                } else {
                    __half h0, l0, h1, l1;
                    hsplit(v0, h0, l0); hsplit(v1, h1, l1);
                    *reinterpret_cast<__half2*>(Chi + zC + o) = __halves2half2(h0, h1);
                    *reinterpret_cast<__half2*>(Clo + zC + o) = __halves2half2(l0, l1);
                }
            }
        }
    }
}

// ---------------------------------------------------------------------------
// FFN2 GEMM: 2 CTAs/SM.  CTA 128x128, BK=64, 8 warps, 3 stages (96 KB/CTA).
// (R9 configuration, unchanged.)
// ---------------------------------------------------------------------------
#define F2_STAGE (2 * TILE_BYTES)      // A tile + B tile = 32 KB
#define F2_SMEM  (3 * F2_STAGE)        // 98304

__device__ __forceinline__ void load_chunk_f2(uint32_t sbase, int st,
    const __half* __restrict__ gA, const __half* __restrict__ gB,
    int K, int k0, int tid)
{
    uint32_t s0 = sbase + (uint32_t)(st * F2_STAGE);
    #pragma unroll
    for (int it = 0; it < 4; it++) {
        int idx = tid + it * 256;
        int r = idx >> 3, c = idx & 7;
        uint32_t so = SWZ(r, c);
        long go = (long)r * K + k0 + c * 8;
        CP_ASYNC16(s0 + so, gA + go);
        CP_ASYNC16(s0 + TILE_BYTES + so, gB + go);
    }
}

template<bool BIAS>
__global__ __launch_bounds__(256, 2)
void hgemm_ffn2(const __half* __restrict__ A0, const __half* __restrict__ B0,
                const float* __restrict__ bias, float* __restrict__ Cf,
                int M, int N, int K, int ntm)
{
    extern __shared__ char smem[];
    const uint32_t sbase = smem_u32(smem);
    const int tid  = threadIdx.x;
    const int wid  = tid >> 5, lane = tid & 31;
    const int wm   = wid & 1,  wn   = wid >> 1;

    int pm = blockIdx.x % ntm, pn = blockIdx.x / ntm;
    long m0 = (long)pm * 128, n0 = (long)pn * 128;
    const __half* gA = A0 + m0 * K;
    const __half* gB = B0 + n0 * K;

    float acc[4][4][4];
    #pragma unroll
    for (int i = 0; i < 4; i++)
        #pragma unroll
        for (int j = 0; j < 4; j++)
            #pragma unroll
            for (int k = 0; k < 4; k++) acc[i][j][k] = 0.f;

    const int ar = lane & 15;
    const int ak = (lane >> 4) << 3;
    const int br = ((lane >> 4) << 3) + (lane & 7);
    const int bk = ((lane >> 3) & 1) << 3;

    load_chunk_f2(sbase, 0, gA, gB, K, 0, tid);    CP_COMMIT();
    load_chunk_f2(sbase, 1, gA, gB, K, BKT, tid);  CP_COMMIT();

    const int nc = K / BKT;
    for (int c = 0; c < nc; c++) {
        CP_WAIT1();
        __syncthreads();
        if (c + 2 < nc)
            load_chunk_f2(sbase, (c + 2) % 3, gA, gB, K, (c + 2) * BKT, tid);
        CP_COMMIT();

        uint32_t s0 = sbase + (uint32_t)((c % 3) * F2_STAGE);
        #pragma unroll
        for (int kb = 0; kb < BKT; kb += 16) {
            uint32_t af[4][4], bf[2][4];
            int aq = (kb + ak) >> 3;
            int bq = (kb + bk) >> 3;
            #pragma unroll
            for (int mt = 0; mt < 4; mt++) {
                int r = wm * 64 + mt * 16 + ar;
                ldsm4(af[mt], s0 + SWZ(r, aq));
            }
            #pragma unroll
            for (int nt = 0; nt < 2; nt++) {
                int r = wn * 32 + nt * 16 + br;
                ldsm4(bf[nt], s0 + TILE_BYTES + SWZ(r, bq));
            }
            #pragma unroll
            for (int mt = 0; mt < 4; mt++)
                #pragma unroll
                for (int n8 = 0; n8 < 4; n8++)
                    mma16816(acc[mt][n8], af[mt], &bf[n8 >> 1][(n8 & 1) * 2]);
        }
    }

    // ---- epilogue ----
    int rb = lane >> 2;
    int cb = (lane & 3) * 2;
    #pragma unroll
    for (int mt = 0; mt < 4; mt++) {
        #pragma unroll
        for (int n8 = 0; n8 < 4; n8++) {
            long col = n0 + wn * 32 + n8 * 8 + cb;
            float bv0 = 0.f, bv1 = 0.f;
            if (BIAS) { bv0 = bias[col]; bv1 = bias[col + 1]; }
            #pragma unroll
            for (int h = 0; h < 2; h++) {
                long row = m0 + wm * 64 + mt * 16 + rb + h * 8;
                *reinterpret_cast<float2*>(Cf + row * (long)N + col) =
                    make_float2(acc[mt][n8][h * 2 + 0] + bv0,
                                acc[mt][n8][h * 2 + 1] + bv1);
            }
        }
    }
}

// ---------------------------------------------------------------------------
// Launch
// ---------------------------------------------------------------------------
extern "C" void kernel_launch(void* const* d_in, const int* in_sizes, int n_in,
                              void* d_out, int out_size) {
    const int*   ids = (const int*)  d_in[0];
    const float* emb = (const float*)d_in[1];
    const float* W1  = (const float*)d_in[2];
    const float* b1  = (const float*)d_in[3];
    const float* W2  = (const float*)d_in[4];
    const float* b2  = (const float*)d_in[5];
    float* out = (float*)d_out;

    float *x, *scores;
    __half *xhi, *xlo, *xThi, *whi, *wlo, *athi, *atlo, *hdhi, *w1t, *w2t;
    cudaGetSymbolAddress((void**)&x,      g_x);
    cudaGetSymbolAddress((void**)&scores, g_scores);
    cudaGetSymbolAddress((void**)&xhi,    g_xhi);
    cudaGetSymbolAddress((void**)&xlo,    g_xlo);
    cudaGetSymbolAddress((void**)&xThi,   g_xThi);
    cudaGetSymbolAddress((void**)&whi,    g_whi);
    cudaGetSymbolAddress((void**)&wlo,    g_wlo);
    cudaGetSymbolAddress((void**)&athi,   g_atthi);
    cudaGetSymbolAddress((void**)&atlo,   g_attlo);
    cudaGetSymbolAddress((void**)&hdhi,   g_hidhi);
    cudaGetSymbolAddress((void**)&w1t,    g_W1t);
    cudaGetSymbolAddress((void**)&w2t,    g_W2t);

    const int SM3  = 4 * 3 * TILE_BYTES;  // MODE3, 3-stage: 196608
    const int SM22 = 3 * 2 * TILE_BYTES;  // MODE2, 2-stage: 98304
    cudaFuncSetAttribute(hgemm<3, 0, false, false, 3, 1>, cudaFuncAttributeMaxDynamicSharedMemorySize, SM3);
    cudaFuncSetAttribute(hgemm<2, 2, false, false, 2, 2>, cudaFuncAttributeMaxDynamicSharedMemorySize, SM22);
    cudaFuncSetAttribute(hgemm<2, 1, true,  true,  2, 2>, cudaFuncAttributeMaxDynamicSharedMemorySize, SM22);
    cudaFuncSetAttribute(hgemm_ffn2<true>, cudaFuncAttributeMaxDynamicSharedMemorySize, F2_SMEM);

    // 0) embedding -> x fp32, x hi/lo fp16
    embed_kernel<<<BATCH * SEQ, 256>>>(ids, emb, x, xhi, xlo);

    // 1) xT single fp16 ([S,E] -> [E,S] per batch)
    {
        dim3 grid(EMBED / 32, SEQ / 32, BATCH);
        transpose_single_kernel<<<grid, dim3(32, 8)>>>(x, xThi, SEQ, EMBED,
                                                       (long)SEQ * EMBED, (long)EMBED * SEQ);
    }
    // 2) W1t + W2t single fp16 (combined launch)
    {
        dim3 grid(VOCAB / 32, HID / 32, 2);
        transpose_weights_kernel<<<grid, dim3(32, 8)>>>(W1, W2, w1t, w2t);
    }

    // 3) scores = x @ x^T   (3-term, 3-stage, fp32 out)  M=N=2048 K=1024
    {
        dim3 grid((SEQ / BMT) * (SEQ / BNT), 1, BATCH);
        hgemm<3, 0, false, false, 3, 1><<<grid, 256, SM3>>>(
            xhi, xlo, xhi, xlo, nullptr, scores, nullptr, nullptr,
            SEQ, SEQ, EMBED, (long)SEQ * EMBED, (long)SEQ * EMBED, (long)SEQ * SEQ,
            SEQ / BMT);
    }

    // 4) softmax -> w hi/lo
    softmax_kernel<<<BATCH * SEQ, 256>>>(scores, whi, wlo);

    // 5) attended = w @ x  (2-term A-split, 2-stage 2CTA/SM, fp16 hi/lo out)
    //    M=2048 N=1024 K=2048
    {
        dim3 grid((SEQ / BMT) * (EMBED / BNT), 1, BATCH);
        hgemm<2, 2, false, false, 2, 2><<<grid, 256, SM22>>>(
            whi, wlo, xThi, nullptr, nullptr, nullptr, athi, atlo,
            SEQ, EMBED, SEQ, (long)SEQ * SEQ, (long)EMBED * SEQ, (long)SEQ * EMBED,
            SEQ / BMT);
    }

    // 6) hidden = relu(att @ W1 + b1)  (2-term A-split, 2-stage 2CTA/SM, fp16 hi out)
    //    M=8192 N=4096 K=1024
    {
        dim3 grid(((BATCH * SEQ) / BMT) * (HID / BNT), 1, 1);
        hgemm<2, 1, true, true, 2, 2><<<grid, 256, SM22>>>(
            athi, atlo, w1t, nullptr, b1, nullptr, hdhi, nullptr,
            BATCH * SEQ, HID, EMBED, 0, 0, 0,
            (BATCH * SEQ) / BMT);
    }

    // 7) logits = hidden @ W2 + b2  (1-term, 2 CTA/SM, fp32 out)  M=8192 N=32000 K=4096
    {
        dim3 grid(((BATCH * SEQ) / 128) * (VOCAB / 128), 1, 1);
        hgemm_ffn2<true><<<grid, 256, F2_SMEM>>>(
            hdhi, w2t, b2, out, BATCH * SEQ, VOCAB, HID, (BATCH * SEQ) / 128);
    }
}

// round 11
// speedup vs baseline: 1.7292x; 1.0417x over previous
#include <cuda_runtime.h>
#include <cuda_fp16.h>
#include <cstdint>

// Problem dims
#define BATCH 4
#define SEQ   2048
#define EMBED 1024
#define HID   4096
#define VOCAB 32000

// ---------------------------------------------------------------------------
// PTX helpers (plain sm_103-legal: cp.async / ldmatrix / mma.sync only)
// ---------------------------------------------------------------------------
__device__ __forceinline__ uint32_t smem_u32(const void* p) {
    uint32_t a;
    asm("{ .reg .u64 t; cvta.to.shared.u64 t, %1; cvt.u32.u64 %0, t; }" : "=r"(a) : "l"(p));
    return a;
}
#define CP_ASYNC16(s, g) \
    asm volatile("cp.async.cg.shared.global [%0], [%1], 16;\n" :: "r"(s), "l"(g))
#define CP_COMMIT() asm volatile("cp.async.commit_group;\n" ::: "memory")
#define CP_WAIT1()  asm volatile("cp.async.wait_group 1;\n" ::: "memory")

__device__ __forceinline__ void ldsm4(uint32_t* r, uint32_t a) {
    asm volatile("ldmatrix.sync.aligned.m8n8.x4.shared.b16 {%0,%1,%2,%3}, [%4];"
        : "=r"(r[0]), "=r"(r[1]), "=r"(r[2]), "=r"(r[3]) : "r"(a));
}
__device__ __forceinline__ void mma16816(float* c, const uint32_t* a, const uint32_t* b) {
    asm volatile(
        "mma.sync.aligned.m16n8k16.row.col.f32.f16.f16.f32 "
        "{%0,%1,%2,%3}, {%4,%5,%6,%7}, {%8,%9}, {%0,%1,%2,%3};"
        : "+f"(c[0]), "+f"(c[1]), "+f"(c[2]), "+f"(c[3])
        : "r"(a[0]), "r"(a[1]), "r"(a[2]), "r"(a[3]), "r"(b[0]), "r"(b[1]));
}

// 128B-row SW128 swizzle: row r, 16B-chunk q (0..7) -> byte offset in tile
#define SWZ(r, q) ((uint32_t)((r) * 128 + ((((q) ^ ((r) & 7))) << 4)))

// fp16 hi/lo split (hi+lo covers ~22 mantissa bits of the fp32 value)
__device__ __forceinline__ void hsplit(float v, __half& h, __half& l) {
    h = __float2half_rn(v);
    l = __float2half_rn(v - __half2float(h));
}

// ---------------------------------------------------------------------------
// Scratch (device globals)
// ---------------------------------------------------------------------------
__device__ float  g_x     [BATCH * SEQ * EMBED];
__device__ __half g_xhi   [BATCH * SEQ * EMBED];
__device__ __half g_xlo   [BATCH * SEQ * EMBED];
__device__ __half g_xThi  [BATCH * EMBED * SEQ];
__device__ float  g_scores[BATCH * SEQ * SEQ];
__device__ __half g_whi   [BATCH * SEQ * SEQ];
__device__ __half g_wlo   [BATCH * SEQ * SEQ];
__device__ __half g_atthi [BATCH * SEQ * EMBED];
__device__ __half g_hidhi [BATCH * SEQ * HID];
__device__ __half g_W1t   [HID * EMBED];
__device__ __half g_W2t   [(size_t)VOCAB * HID];

// ---------------------------------------------------------------------------
// Embedding gather: x fp32 + fp16 hi/lo
// ---------------------------------------------------------------------------
__global__ void embed_kernel(const int* __restrict__ ids, const float* __restrict__ emb,
                             float* __restrict__ x,
                             __half* __restrict__ xhi, __half* __restrict__ xlo) {
    int row = blockIdx.x;
    int id  = ids[row];
    int t = threadIdx.x;
    float4 v = reinterpret_cast<const float4*>(emb + (long)id * EMBED)[t];
    reinterpret_cast<float4*>(x + (long)row * EMBED)[t] = v;
    __half h0, l0, h1, l1, h2, l2, h3, l3;
    hsplit(v.x, h0, l0); hsplit(v.y, h1, l1); hsplit(v.z, h2, l2); hsplit(v.w, h3, l3);
    __half2* dh = reinterpret_cast<__half2*>(xhi + (long)row * EMBED) + t * 2;
    __half2* dl = reinterpret_cast<__half2*>(xlo + (long)row * EMBED) + t * 2;
    dh[0] = __halves2half2(h0, h1); dh[1] = __halves2half2(h2, h3);
    dl[0] = __halves2half2(l0, l1); dl[1] = __halves2half2(l2, l3);
}

// ---------------------------------------------------------------------------
// Transpose fp32 [R,C] -> single fp16 [C,R], batched via z (for xT)
// ---------------------------------------------------------------------------
__global__ void transpose_single_kernel(const float* __restrict__ in,
                                        __half* __restrict__ o,
                                        int R, int C, long sIn, long sOut) {
    __shared__ float t[32][33];
    long z = blockIdx.z;
    in += z * sIn;
    o  += z * sOut;
    int c0 = blockIdx.x * 32, r0 = blockIdx.y * 32;
    int tx = threadIdx.x, ty = threadIdx.y;
    #pragma unroll
    for (int i = 0; i < 32; i += 8)
        t[ty + i][tx] = in[(long)(r0 + ty + i) * C + c0 + tx];
    __syncthreads();
    #pragma unroll
    for (int i = 0; i < 32; i += 8) {
        long oo = (long)(c0 + ty + i) * R + r0 + tx;
        o[oo] = __float2half_rn(t[tx][ty + i]);
    }
}

// ---------------------------------------------------------------------------
// Combined weight transpose: z=0 -> W1 [E,H] -> w1t [H,E]
//                            z=1 -> W2 [H,V] -> w2t [V,H]
// ---------------------------------------------------------------------------
__global__ void transpose_weights_kernel(const float* __restrict__ W1,
                                         const float* __restrict__ W2,
                                         __half* __restrict__ w1t,
                                         __half* __restrict__ w2t) {
    __shared__ float t[32][33];
    const float* in; __half* outp; int R, C;
    if (blockIdx.z == 0) {
        if (blockIdx.x >= HID / 32 || blockIdx.y >= EMBED / 32) return;
        in = W1; outp = w1t; R = EMBED; C = HID;
    } else {
        in = W2; outp = w2t; R = HID; C = VOCAB;
    }
    int c0 = blockIdx.x * 32, r0 = blockIdx.y * 32;
    int tx = threadIdx.x, ty = threadIdx.y;
    #pragma unroll
    for (int i = 0; i < 32; i += 8)
        t[ty + i][tx] = in[(long)(r0 + ty + i) * C + c0 + tx];
    __syncthreads();
    #pragma unroll
    for (int i = 0; i < 32; i += 8) {
        long o = (long)(c0 + ty + i) * R + r0 + tx;
        outp[o] = __float2half_rn(t[tx][ty + i]);
    }
}

// ---------------------------------------------------------------------------
// Softmax rows (fp32 in) -> fp16 hi/lo weights
// ---------------------------------------------------------------------------
__global__ __launch_bounds__(256)
void softmax_kernel(const float* __restrict__ scores,
                    __half* __restrict__ whi, __half* __restrict__ wlo) {
    __shared__ float red[256];
    const float* row = scores + (long)blockIdx.x * SEQ;
    __half* oh = whi + (long)blockIdx.x * SEQ;
    __half* ol = wlo + (long)blockIdx.x * SEQ;
    const int tid = threadIdx.x;

    float v[8];
    float lmax = -3.402823466e+38f;
    #pragma unroll
    for (int i = 0; i < 8; i++) { v[i] = row[tid + i * 256]; lmax = fmaxf(lmax, v[i]); }
    red[tid] = lmax; __syncthreads();
    #pragma unroll
    for (int s = 128; s > 0; s >>= 1) { if (tid < s) red[tid] = fmaxf(red[tid], red[tid + s]); __syncthreads(); }
    float m = red[0]; __syncthreads();

    float lsum = 0.f;
    #pragma unroll
    for (int i = 0; i < 8; i++) { v[i] = __expf(v[i] - m); lsum += v[i]; }
    red[tid] = lsum; __syncthreads();
    #pragma unroll
    for (int s = 128; s > 0; s >>= 1) { if (tid < s) red[tid] += red[tid + s]; __syncthreads(); }
    float inv = 1.f / red[0];
    #pragma unroll
    for (int i = 0; i < 8; i++) {
        float w = v[i] * inv;
        __half h, l; hsplit(w, h, l);
        oh[tid + i * 256] = h; ol[tid + i * 256] = l;
    }
}

// ---------------------------------------------------------------------------
// HMMA split-fp16 GEMM:  C[M,N] = A[M,K] * B[N,K]^T
// MODE=2: A0*B0 + A1*B0 (3 tiles/stage).  MODE=3: + A0*B1 (4 tiles/stage).
// OUT=0: fp32   OUT=1: fp16 hi only   OUT=2: fp16 hi/lo
// SYM: C symmetric (M==N, A==B); grid covers upper-triangular tiles only,
//      off-diagonal tiles mirrored via smem-staged transposed store.
// NST=3,MINB=1: 3-stage single-CTA.  NST=2,MINB=2: 2-stage, 2 CTAs/SM.
// ---------------------------------------------------------------------------
#define BMT 128
#define BNT 128
#define BKT 64
#define TILE_BYTES 16384    // 128 rows x 128 B

template<int TPS>
__device__ __forceinline__ void load_chunk(uint32_t sbase, int st,
    const __half* __restrict__ gA0, const __half* __restrict__ gA1,
    const __half* __restrict__ gB0, const __half* __restrict__ gB1,
    int K, int k0, int tid)
{
    uint32_t s0 = sbase + (uint32_t)(st * TPS * TILE_BYTES);
    #pragma unroll
    for (int it = 0; it < 4; it++) {
        int idx = tid + it * 256;
        int r = idx >> 3, c = idx & 7;
        uint32_t so = SWZ(r, c);
        long go = (long)r * K + k0 + c * 8;
        CP_ASYNC16(s0 + 0 * TILE_BYTES + so, gA0 + go);
        CP_ASYNC16(s0 + 1 * TILE_BYTES + so, gA1 + go);
        CP_ASYNC16(s0 + 2 * TILE_BYTES + so, gB0 + go);
        if (TPS == 4) CP_ASYNC16(s0 + 3 * TILE_BYTES + so, gB1 + go);
    }
}

template<int MODE, int OUT, bool BIAS, bool RELU, int NST, int MINB, bool SYM>
__global__ __launch_bounds__(256, MINB)
void hgemm(const __half* __restrict__ A0, const __half* __restrict__ A1,
           const __half* __restrict__ B0, const __half* __restrict__ B1,
           const float* __restrict__ bias,
           float* __restrict__ Cf, __half* __restrict__ Chi, __half* __restrict__ Clo,
           int M, int N, int K, long sA, long sB, long sC, int ntm)
{
    extern __shared__ char smem[];
    const uint32_t sbase = smem_u32(smem);
    const int tid  = threadIdx.x;
    const int wid  = tid >> 5, lane = tid & 31;
    const int wm   = wid & 1,  wn   = wid >> 1;
    constexpr int TPS = (MODE == 3) ? 4 : 3;

    int pm, pn;
    if (SYM) {
        int t = blockIdx.x, i = 0;
        while (t >= ntm - i) { t -= ntm - i; i++; }
        pm = i; pn = i + t;
    } else {
        pm = blockIdx.x % ntm; pn = blockIdx.x / ntm;
    }
    long m0 = (long)pm * BMT, n0 = (long)pn * BNT;
    long zb = blockIdx.z;
    const __half* gA0 = A0 + zb * sA + m0 * K;
    const __half* gA1 = A1 + zb * sA + m0 * K;
    const __half* gB0 = B0 + zb * sB + n0 * K;
    const __half* gB1 = (MODE == 3) ? (B1 + zb * sB + n0 * K) : gB0;

    float acc[4][4][4];
    #pragma unroll
    for (int i = 0; i < 4; i++)
        #pragma unroll
        for (int j = 0; j < 4; j++)
            #pragma unroll
            for (int k = 0; k < 4; k++) acc[i][j][k] = 0.f;

    const int ar = lane & 15;
    const int ak = (lane >> 4) << 3;
    const int br = ((lane >> 4) << 3) + (lane & 7);
    const int bk = ((lane >> 3) & 1) << 3;

    const int nc = K / BKT;

    auto compute_stage = [&](uint32_t s0) {
        #pragma unroll
        for (int kb = 0; kb < BKT; kb += 16) {
            uint32_t a0f[4][4], a1f[4][4], b0f[2][4], b1f[2][4];
            int aq = (kb + ak) >> 3;
            int bq = (kb + bk) >> 3;
            #pragma unroll
            for (int mt = 0; mt < 4; mt++) {
                int r = wm * 64 + mt * 16 + ar;
                uint32_t ad = s0 + SWZ(r, aq);
                ldsm4(a0f[mt], ad);
                ldsm4(a1f[mt], ad + TILE_BYTES);
            }
            #pragma unroll
            for (int nt = 0; nt < 2; nt++) {
                int r = wn * 32 + nt * 16 + br;
                uint32_t bd = s0 + 2 * TILE_BYTES + SWZ(r, bq);
                ldsm4(b0f[nt], bd);
                if (MODE == 3) ldsm4(b1f[nt], bd + TILE_BYTES);
            }
            #pragma unroll
            for (int mt = 0; mt < 4; mt++)
                #pragma unroll
                for (int n8 = 0; n8 < 4; n8++) {
                    const uint32_t* b = &b0f[n8 >> 1][(n8 & 1) * 2];
                    mma16816(acc[mt][n8], a0f[mt], b);
                    mma16816(acc[mt][n8], a1f[mt], b);
                    if (MODE == 3)
                        mma16816(acc[mt][n8], a0f[mt], &b1f[n8 >> 1][(n8 & 1) * 2]);
                }
        }
    };

    if (NST == 3) {
        load_chunk<TPS>(sbase, 0, gA0, gA1, gB0, gB1, K, 0, tid);   CP_COMMIT();
        load_chunk<TPS>(sbase, 1, gA0, gA1, gB0, gB1, K, BKT, tid); CP_COMMIT();
        for (int c = 0; c < nc; c++) {
            CP_WAIT1();
            __syncthreads();
            if (c + 2 < nc)
                load_chunk<TPS>(sbase, (c + 2) % 3, gA0, gA1, gB0, gB1, K, (c + 2) * BKT, tid);
            CP_COMMIT();
            compute_stage(sbase + (uint32_t)((c % 3) * TPS * TILE_BYTES));
        }
    } else {
        load_chunk<TPS>(sbase, 0, gA0, gA1, gB0, gB1, K, 0, tid); CP_COMMIT();
        for (int c = 0; c < nc; c++) {
            if (c + 1 < nc) {
                load_chunk<TPS>(sbase, (c + 1) & 1, gA0, gA1, gB0, gB1, K, (c + 1) * BKT, tid);
            }
            CP_COMMIT();
            CP_WAIT1();
            __syncthreads();
            compute_stage(sbase + (uint32_t)((c & 1) * TPS * TILE_BYTES));
            __syncthreads();
        }
    }

    // ---- epilogue ----
    long zC = zb * sC;
    int rb = lane >> 2;
    int cb = (lane & 3) * 2;
    #pragma unroll
    for (int mt = 0; mt < 4; mt++) {
        #pragma unroll
        for (int n8 = 0; n8 < 4; n8++) {
            long col = n0 + wn * 32 + n8 * 8 + cb;
            float bv0 = 0.f, bv1 = 0.f;
            if (BIAS) { bv0 = bias[col]; bv1 = bias[col + 1]; }
            #pragma unroll
            for (int h = 0; h < 2; h++) {
                long row = m0 + wm * 64 + mt * 16 + rb + h * 8;
                float v0 = acc[mt][n8][h * 2 + 0] + bv0;
                float v1 = acc[mt][n8][h * 2 + 1] + bv1;
                if (RELU) { v0 = fmaxf(v0, 0.f); v1 = fmaxf(v1, 0.f); }
                long o = row * (long)N + col;
                if (OUT == 0) {
                    *reinterpret_cast<float2*>(Cf + zC + o) = make_float2(v0, v1);
                } else if (OUT == 1) {
                    *reinterpret_cast<__half2*>(Chi + zC + o) =
                        __halves2half2(__float2half_rn(v0), __float2half_rn(v1));
                } else {
                    __half h0, l0, h1, l1;
                    hsplit(v0, h0, l0); hsplit(v1, h1, l1);
                    *reinterpret_cast<__half2*>(Chi + zC + o) = __halves2half2(h0, h1);
                    *reinterpret_cast<__half2*>(Clo + zC + o) = __halves2half2(l0, l1);
                }
            }
        }
    }

    // ---- symmetric mirror: write transposed tile at (pn, pm) ----
    if (SYM && OUT == 0) {
        if (pm != pn) {
            __syncthreads();   // all warps done with pipeline smem + epilogue
            float* stg = reinterpret_cast<float*>(smem);   // 128 x 129 floats
            #pragma unroll
            for (int mt = 0; mt < 4; mt++)
                #pragma unroll
                for (int n8 = 0; n8 < 4; n8++) {
                    int colb = wn * 32 + n8 * 8 + cb;
                    #pragma unroll
                    for (int h = 0; h < 2; h++) {
                        int rowb = wm * 64 + mt * 16 + rb + h * 8;
                        stg[rowb * 129 + colb]     = acc[mt][n8][h * 2 + 0];
                        stg[rowb * 129 + colb + 1] = acc[mt][n8][h * 2 + 1];
                    }
                }
            __syncthreads();
            // transposed coalesced store: C[(n0+rr), m0+cc] = stg[cc][rr]
            #pragma unroll
            for (int it = 0; it < 64; it++) {
                int idx = tid + it * 256;
                int rr = idx >> 7, cc = idx & 127;
                Cf[zC + (n0 + rr) * (long)N + m0 + cc] = stg[cc * 129 + rr];
            }
        }
    }
}

// ---------------------------------------------------------------------------
// 1-term HMMA GEMM (FFN1 + FFN2): 2 CTAs/SM, CTA 128x128, BK=64, 8 warps,
// 3 stages (96 KB/CTA).  OUT=0: fp32.  OUT=1: fp16 hi.
// ---------------------------------------------------------------------------
#define F2_STAGE (2 * TILE_BYTES)      // A tile + B tile = 32 KB
#define F2_SMEM  (3 * F2_STAGE)        // 98304

__device__ __forceinline__ void load_chunk_1t(uint32_t sbase, int st,
    const __half* __restrict__ gA, const __half* __restrict__ gB,
    int K, int k0, int tid)
{
    uint32_t s0 = sbase + (uint32_t)(st * F2_STAGE);
    #pragma unroll
    for (int it = 0; it < 4; it++) {
        int idx = tid + it * 256;
        int r = idx >> 3, c = idx & 7;
        uint32_t so = SWZ(r, c);
        long go = (long)r * K + k0 + c * 8;
        CP_ASYNC16(s0 + so, gA + go);
        CP_ASYNC16(s0 + TILE_BYTES + so, gB + go);
    }
}

template<int OUT, bool BIAS, bool RELU>
__global__ __launch_bounds__(256, 2)
void hgemm_1t(const __half* __restrict__ A0, const __half* __restrict__ B0,
              const float* __restrict__ bias,
              float* __restrict__ Cf, __half* __restrict__ Chi,
              int M, int N, int K, int ntm)
{
    extern __shared__ char smem[];
    const uint32_t sbase = smem_u32(smem);
    const int tid  = threadIdx.x;
    const int wid  = tid >> 5, lane = tid & 31;
    const int wm   = wid & 1,  wn   = wid >> 1;

    int pm = blockIdx.x % ntm, pn = blockIdx.x / ntm;
    long m0 = (long)pm * 128, n0 = (long)pn * 128;
    const __half* gA = A0 + m0 * K;
    const __half* gB = B0 + n0 * K;

    float acc[4][4][4];
    #pragma unroll
    for (int i = 0; i < 4; i++)
        #pragma unroll
        for (int j = 0; j < 4; j++)
            #pragma unroll
            for (int k = 0; k < 4; k++) acc[i][j][k] = 0.f;

    const int ar = lane & 15;
    const int ak = (lane >> 4) << 3;
    const int br = ((lane >> 4) << 3) + (lane & 7);
    const int bk = ((lane >> 3) & 1) << 3;

    load_chunk_1t(sbase, 0, gA, gB, K, 0, tid);    CP_COMMIT();
    load_chunk_1t(sbase, 1, gA, gB, K, BKT, tid);  CP_COMMIT();

    const int nc = K / BKT;
    for (int c = 0; c < nc; c++) {
        CP_WAIT1();
        __syncthreads();
        if (c + 2 < nc)
            load_chunk_1t(sbase, (c + 2) % 3, gA, gB, K, (c + 2) * BKT, tid);
        CP_COMMIT();

        uint32_t s0 = sbase + (uint32_t)((c % 3) * F2_STAGE);
        #pragma unroll
        for (int kb = 0; kb < BKT; kb += 16) {
            uint32_t af[4][4], bf[2][4];
            int aq = (kb + ak) >> 3;
            int bq = (kb + bk) >> 3;
            #pragma unroll
            for (int mt = 0; mt < 4; mt++) {
                int r = wm * 64 + mt * 16 + ar;
                ldsm4(af[mt], s0 + SWZ(r, aq));
            }
            #pragma unroll
            for (int nt = 0; nt < 2; nt++) {
                int r = wn * 32 + nt * 16 + br;
                ldsm4(bf[nt], s0 + TILE_BYTES + SWZ(r, bq));
            }
            #pragma unroll
            for (int mt = 0; mt < 4; mt++)
                #pragma unroll
                for (int n8 = 0; n8 < 4; n8++)
                    mma16816(acc[mt][n8], af[mt], &bf[n8 >> 1][(n8 & 1) * 2]);
        }
    }

    // ---- epilogue ----
    int rb = lane >> 2;
    int cb = (lane & 3) * 2;
    #pragma unroll
    for (int mt = 0; mt < 4; mt++) {
        #pragma unroll
        for (int n8 = 0; n8 < 4; n8++) {
            long col = n0 + wn * 32 + n8 * 8 + cb;
            float bv0 = 0.f, bv1 = 0.f;
            if (BIAS) { bv0 = bias[col]; bv1 = bias[col + 1]; }
            #pragma unroll
            for (int h = 0; h < 2; h++) {
                long row = m0 + wm * 64 + mt * 16 + rb + h * 8;
                float v0 = acc[mt][n8][h * 2 + 0] + bv0;
                float v1 = acc[mt][n8][h * 2 + 1] + bv1;
                if (RELU) { v0 = fmaxf(v0, 0.f); v1 = fmaxf(v1, 0.f); }
                long o = row * (long)N + col;
                if (OUT == 0) {
                    *reinterpret_cast<float2*>(Cf + o) = make_float2(v0, v1);
                } else {
                    *reinterpret_cast<__half2*>(Chi + o) =
                        __halves2half2(__float2half_rn(v0), __float2half_rn(v1));
                }
            }
        }
    }
}

// ---------------------------------------------------------------------------
// Launch
// ---------------------------------------------------------------------------
extern "C" void kernel_launch(void* const* d_in, const int* in_sizes, int n_in,
                              void* d_out, int out_size) {
    const int*   ids = (const int*)  d_in[0];
    const float* emb = (const float*)d_in[1];
    const float* W1  = (const float*)d_in[2];
    const float* b1  = (const float*)d_in[3];
    const float* W2  = (const float*)d_in[4];
    const float* b2  = (const float*)d_in[5];
    float* out = (float*)d_out;

    float *x, *scores;
    __half *xhi, *xlo, *xThi, *whi, *wlo, *athi, *hdhi, *w1t, *w2t;
    cudaGetSymbolAddress((void**)&x,      g_x);
    cudaGetSymbolAddress((void**)&scores, g_scores);
    cudaGetSymbolAddress((void**)&xhi,    g_xhi);
    cudaGetSymbolAddress((void**)&xlo,    g_xlo);
    cudaGetSymbolAddress((void**)&xThi,   g_xThi);
    cudaGetSymbolAddress((void**)&whi,    g_whi);
    cudaGetSymbolAddress((void**)&wlo,    g_wlo);
    cudaGetSymbolAddress((void**)&athi,   g_atthi);
    cudaGetSymbolAddress((void**)&hdhi,   g_hidhi);
    cudaGetSymbolAddress((void**)&w1t,    g_W1t);
    cudaGetSymbolAddress((void**)&w2t,    g_W2t);

    const int SM3  = 4 * 3 * TILE_BYTES;  // MODE3, 3-stage: 196608
    const int SM22 = 3 * 2 * TILE_BYTES;  // MODE2, 2-stage: 98304
    cudaFuncSetAttribute(hgemm<3, 0, false, false, 3, 1, true>,  cudaFuncAttributeMaxDynamicSharedMemorySize, SM3);
    cudaFuncSetAttribute(hgemm<2, 1, false, false, 2, 2, false>, cudaFuncAttributeMaxDynamicSharedMemorySize, SM22);
    cudaFuncSetAttribute(hgemm_1t<1, true, true>,  cudaFuncAttributeMaxDynamicSharedMemorySize, F2_SMEM);
    cudaFuncSetAttribute(hgemm_1t<0, true, false>, cudaFuncAttributeMaxDynamicSharedMemorySize, F2_SMEM);

    // 0) embedding -> x fp32, x hi/lo fp16
    embed_kernel<<<BATCH * SEQ, 256>>>(ids, emb, x, xhi, xlo);

    // 1) xT single fp16 ([S,E] -> [E,S] per batch)
    {
        dim3 grid(EMBED / 32, SEQ / 32, BATCH);
        transpose_single_kernel<<<grid, dim3(32, 8)>>>(x, xThi, SEQ, EMBED,
                                                       (long)SEQ * EMBED, (long)EMBED * SEQ);
    }
    // 2) W1t + W2t single fp16 (combined launch)
    {
        dim3 grid(VOCAB / 32, HID / 32, 2);
        transpose_weights_kernel<<<grid, dim3(32, 8)>>>(W1, W2, w1t, w2t);
    }

    // 3) scores = x @ x^T  (3-term, 3-stage, SYMMETRIC: upper-tri tiles + mirror)
    //    M=N=2048 K=1024; 16x17/2 = 136 tiles per batch
    {
        const int ntm = SEQ / BMT;                 // 16
        dim3 grid(ntm * (ntm + 1) / 2, 1, BATCH);  // 136
        hgemm<3, 0, false, false, 3, 1, true><<<grid, 256, SM3>>>(
            xhi, xlo, xhi, xlo, nullptr, scores, nullptr, nullptr,
            SEQ, SEQ, EMBED, (long)SEQ * EMBED, (long)SEQ * EMBED, (long)SEQ * SEQ,
            ntm);
    }

    // 4) softmax -> w hi/lo
    softmax_kernel<<<BATCH * SEQ, 256>>>(scores, whi, wlo);

    // 5) attended = w @ x  (2-term A-split, 2-stage 2CTA/SM, fp16 hi out)
    //    M=2048 N=1024 K=2048
    {
        dim3 grid((SEQ / BMT) * (EMBED / BNT), 1, BATCH);
        hgemm<2, 1, false, false, 2, 2, false><<<grid, 256, SM22>>>(
            whi, wlo, xThi, nullptr, nullptr, nullptr, athi, nullptr,
            SEQ, EMBED, SEQ, (long)SEQ * SEQ, (long)EMBED * SEQ, (long)SEQ * EMBED,
            SEQ / BMT);
    }

    // 6) hidden = relu(att @ W1 + b1)  (1-term, 2CTA/SM, fp16 hi out)
    //    M=8192 N=4096 K=1024
    {
        dim3 grid(((BATCH * SEQ) / 128) * (HID / 128), 1, 1);
        hgemm_1t<1, true, true><<<grid, 256, F2_SMEM>>>(
            athi, w1t, b1, nullptr, hdhi,
            BATCH * SEQ, HID, EMBED, (BATCH * SEQ) / 128);
    }

    // 7) logits = hidden @ W2 + b2  (1-term, 2CTA/SM, fp32 out)
    //    M=8192 N=32000 K=4096
    {
        dim3 grid(((BATCH * SEQ) / 128) * (VOCAB / 128), 1, 1);
        hgemm_1t<0, true, false><<<grid, 256, F2_SMEM>>>(
            hdhi, w2t, b2, out, nullptr,
            BATCH * SEQ, VOCAB, HID, (BATCH * SEQ) / 128);
    }
}

// round 12
// speedup vs baseline: 1.7511x; 1.0127x over previous
#include <cuda_runtime.h>
#include <cuda_fp16.h>
#include <cstdint>

// Problem dims
#define BATCH 4
#define SEQ   2048
#define EMBED 1024
#define HID   4096
#define VOCAB 32000

// ---------------------------------------------------------------------------
// PTX helpers (plain sm_103-legal: cp.async / ldmatrix / mma.sync only)
// ---------------------------------------------------------------------------
__device__ __forceinline__ uint32_t smem_u32(const void* p) {
    uint32_t a;
    asm("{ .reg .u64 t; cvta.to.shared.u64 t, %1; cvt.u32.u64 %0, t; }" : "=r"(a) : "l"(p));
    return a;
}
#define CP_ASYNC16(s, g) \
    asm volatile("cp.async.cg.shared.global [%0], [%1], 16;\n" :: "r"(s), "l"(g))
#define CP_COMMIT() asm volatile("cp.async.commit_group;\n" ::: "memory")
#define CP_WAIT1()  asm volatile("cp.async.wait_group 1;\n" ::: "memory")

__device__ __forceinline__ void ldsm4(uint32_t* r, uint32_t a) {
    asm volatile("ldmatrix.sync.aligned.m8n8.x4.shared.b16 {%0,%1,%2,%3}, [%4];"
        : "=r"(r[0]), "=r"(r[1]), "=r"(r[2]), "=r"(r[3]) : "r"(a));
}
__device__ __forceinline__ void mma16816(float* c, const uint32_t* a, const uint32_t* b) {
    asm volatile(
        "mma.sync.aligned.m16n8k16.row.col.f32.f16.f16.f32 "
        "{%0,%1,%2,%3}, {%4,%5,%6,%7}, {%8,%9}, {%0,%1,%2,%3};"
        : "+f"(c[0]), "+f"(c[1]), "+f"(c[2]), "+f"(c[3])
        : "r"(a[0]), "r"(a[1]), "r"(a[2]), "r"(a[3]), "r"(b[0]), "r"(b[1]));
}

// 128B-row SW128 swizzle: row r, 16B-chunk q (0..7) -> byte offset in tile
#define SWZ(r, q) ((uint32_t)((r) * 128 + ((((q) ^ ((r) & 7))) << 4)))

// fp16 hi/lo split (hi+lo covers ~22 mantissa bits of the fp32 value)
__device__ __forceinline__ void hsplit(float v, __half& h, __half& l) {
    h = __float2half_rn(v);
    l = __float2half_rn(v - __half2float(h));
}

// ---------------------------------------------------------------------------
// Scratch (device globals)
// ---------------------------------------------------------------------------
__device__ __half g_xhi   [BATCH * SEQ * EMBED];
__device__ __half g_xlo   [BATCH * SEQ * EMBED];
__device__ __half g_xThi  [BATCH * EMBED * SEQ];
__device__ float  g_scores[BATCH * SEQ * SEQ];
__device__ __half g_whi   [BATCH * SEQ * SEQ];
__device__ __half g_atthi [BATCH * SEQ * EMBED];
__device__ __half g_hidhi [BATCH * SEQ * HID];
__device__ __half g_W1t   [HID * EMBED];
__device__ __half g_W2t   [(size_t)VOCAB * HID];

// ---------------------------------------------------------------------------
// Embedding gather: fp16 hi/lo only
// ---------------------------------------------------------------------------
__global__ void embed_kernel(const int* __restrict__ ids, const float* __restrict__ emb,
                             __half* __restrict__ xhi, __half* __restrict__ xlo) {
    int row = blockIdx.x;
    int id  = ids[row];
    int t = threadIdx.x;
    float4 v = reinterpret_cast<const float4*>(emb + (long)id * EMBED)[t];
    __half h0, l0, h1, l1, h2, l2, h3, l3;
    hsplit(v.x, h0, l0); hsplit(v.y, h1, l1); hsplit(v.z, h2, l2); hsplit(v.w, h3, l3);
    __half2* dh = reinterpret_cast<__half2*>(xhi + (long)row * EMBED) + t * 2;
    __half2* dl = reinterpret_cast<__half2*>(xlo + (long)row * EMBED) + t * 2;
    dh[0] = __halves2half2(h0, h1); dh[1] = __halves2half2(h2, h3);
    dl[0] = __halves2half2(l0, l1); dl[1] = __halves2half2(l2, l3);
}

// ---------------------------------------------------------------------------
// xT gather-transpose: xThi[b][e][s] = fp16(emb[ids[b][s]][e])
// 32x32 tiles, float2 loads, __half2 stores. Block (16,16).
// ---------------------------------------------------------------------------
__global__ void xt_gather_kernel(const int* __restrict__ ids, const float* __restrict__ emb,
                                 __half* __restrict__ o) {
    __shared__ float t[32][33];
    long z = blockIdx.z;
    const int* idz = ids + z * SEQ;
    o += z * (long)EMBED * SEQ;
    int c0 = blockIdx.x * 32;   // embed dims
    int r0 = blockIdx.y * 32;   // tokens
    int tx = threadIdx.x, ty = threadIdx.y;
    #pragma unroll
    for (int i = 0; i < 32; i += 16) {
        int id = idz[r0 + ty + i];
        float2 v = *reinterpret_cast<const float2*>(emb + (long)id * EMBED + c0 + 2 * tx);
        t[ty + i][2 * tx]     = v.x;
        t[ty + i][2 * tx + 1] = v.y;
    }
    __syncthreads();
    #pragma unroll
    for (int i = 0; i < 32; i += 16) {
        int cc = ty + i;
        __half2 h = __halves2half2(__float2half_rn(t[2 * tx][cc]),
                                   __float2half_rn(t[2 * tx + 1][cc]));
        *reinterpret_cast<__half2*>(o + (long)(c0 + cc) * SEQ + r0 + 2 * tx) = h;
    }
}

// ---------------------------------------------------------------------------
// Combined weight transpose (vectorized): z=0 W1 [E,H]->[H,E], z=1 W2 [H,V]->[V,H]
// ---------------------------------------------------------------------------
__global__ void transpose_weights_kernel(const float* __restrict__ W1,
                                         const float* __restrict__ W2,
                                         __half* __restrict__ w1t,
                                         __half* __restrict__ w2t) {
    __shared__ float t[32][33];
    const float* in; __half* outp; int R, C;
    if (blockIdx.z == 0) {
        if (blockIdx.x >= HID / 32 || blockIdx.y >= EMBED / 32) return;
        in = W1; outp = w1t; R = EMBED; C = HID;
    } else {
        in = W2; outp = w2t; R = HID; C = VOCAB;
    }
    int c0 = blockIdx.x * 32, r0 = blockIdx.y * 32;
    int tx = threadIdx.x, ty = threadIdx.y;
    #pragma unroll
    for (int i = 0; i < 32; i += 16) {
        float2 v = *reinterpret_cast<const float2*>(in + (long)(r0 + ty + i) * C + c0 + 2 * tx);
        t[ty + i][2 * tx]     = v.x;
        t[ty + i][2 * tx + 1] = v.y;
    }
    __syncthreads();
    #pragma unroll
    for (int i = 0; i < 32; i += 16) {
        int cc = ty + i;
        __half2 h = __halves2half2(__float2half_rn(t[2 * tx][cc]),
                                   __float2half_rn(t[2 * tx + 1][cc]));
        *reinterpret_cast<__half2*>(outp + (long)(c0 + cc) * R + r0 + 2 * tx) = h;
    }
}

// ---------------------------------------------------------------------------
// Softmax rows (fp32 in) -> fp16 hi weights only
// ---------------------------------------------------------------------------
__global__ __launch_bounds__(256)
void softmax_kernel(const float* __restrict__ scores, __half* __restrict__ whi) {
    __shared__ float red[256];
    const float* row = scores + (long)blockIdx.x * SEQ;
    __half* oh = whi + (long)blockIdx.x * SEQ;
    const int tid = threadIdx.x;

    float v[8];
    float lmax = -3.402823466e+38f;
    #pragma unroll
    for (int i = 0; i < 8; i++) { v[i] = row[tid + i * 256]; lmax = fmaxf(lmax, v[i]); }
    red[tid] = lmax; __syncthreads();
    #pragma unroll
    for (int s = 128; s > 0; s >>= 1) { if (tid < s) red[tid] = fmaxf(red[tid], red[tid + s]); __syncthreads(); }
    float m = red[0]; __syncthreads();

    float lsum = 0.f;
    #pragma unroll
    for (int i = 0; i < 8; i++) { v[i] = __expf(v[i] - m); lsum += v[i]; }
    red[tid] = lsum; __syncthreads();
    #pragma unroll
    for (int s = 128; s > 0; s >>= 1) { if (tid < s) red[tid] += red[tid + s]; __syncthreads(); }
    float inv = 1.f / red[0];
    #pragma unroll
    for (int i = 0; i < 8; i++)
        oh[tid + i * 256] = __float2half_rn(v[i] * inv);
}

// ---------------------------------------------------------------------------
// 3-term split-fp16 symmetric GEMM (scores):  C = A*A^T, upper-tri tiles + mirror
// CTA 128x128, BK=64, 8 warps, 3 stages. (R11 configuration, unchanged.)
// ---------------------------------------------------------------------------
#define BMT 128
#define BKT 64
#define TILE_BYTES 16384    // 128 rows x 128 B

__device__ __forceinline__ void load_chunk_sym(uint32_t sbase, int st,
    const __half* __restrict__ gA0, const __half* __restrict__ gA1,
    const __half* __restrict__ gB0, const __half* __restrict__ gB1,
    int K, int k0, int tid)
{
    uint32_t s0 = sbase + (uint32_t)(st * 4 * TILE_BYTES);
    #pragma unroll
    for (int it = 0; it < 4; it++) {
        int idx = tid + it * 256;
        int r = idx >> 3, c = idx & 7;
        uint32_t so = SWZ(r, c);
        long go = (long)r * K + k0 + c * 8;
        CP_ASYNC16(s0 + 0 * TILE_BYTES + so, gA0 + go);
        CP_ASYNC16(s0 + 1 * TILE_BYTES + so, gA1 + go);
        CP_ASYNC16(s0 + 2 * TILE_BYTES + so, gB0 + go);
        CP_ASYNC16(s0 + 3 * TILE_BYTES + so, gB1 + go);
    }
}

__global__ __launch_bounds__(256, 1)
void hgemm_sym(const __half* __restrict__ A0, const __half* __restrict__ A1,
               float* __restrict__ Cf, int N, int K, long sA, long sC, int ntm)
{
    extern __shared__ char smem[];
    const uint32_t sbase = smem_u32(smem);
    const int tid  = threadIdx.x;
    const int wid  = tid >> 5, lane = tid & 31;
    const int wm   = wid & 1,  wn   = wid >> 1;

    int t0 = blockIdx.x, i0 = 0;
    while (t0 >= ntm - i0) { t0 -= ntm - i0; i0++; }
    int pm = i0, pn = i0 + t0;
    long m0 = (long)pm * BMT, n0 = (long)pn * BMT;
    long zb = blockIdx.z;
    const __half* gA0 = A0 + zb * sA + m0 * K;
    const __half* gA1 = A1 + zb * sA + m0 * K;
    const __half* gB0 = A0 + zb * sA + n0 * K;
    const __half* gB1 = A1 + zb * sA + n0 * K;

    float acc[4][4][4];
    #pragma unroll
    for (int i = 0; i < 4; i++)
        #pragma unroll
        for (int j = 0; j < 4; j++)
            #pragma unroll
            for (int k = 0; k < 4; k++) acc[i][j][k] = 0.f;

    const int ar = lane & 15;
    const int ak = (lane >> 4) << 3;
    const int br = ((lane >> 4) << 3) + (lane & 7);
    const int bk = ((lane >> 3) & 1) << 3;

    load_chunk_sym(sbase, 0, gA0, gA1, gB0, gB1, K, 0, tid);   CP_COMMIT();
    load_chunk_sym(sbase, 1, gA0, gA1, gB0, gB1, K, BKT, tid); CP_COMMIT();

    const int nc = K / BKT;
    for (int c = 0; c < nc; c++) {
        CP_WAIT1();
        __syncthreads();
        if (c + 2 < nc)
            load_chunk_sym(sbase, (c + 2) % 3, gA0, gA1, gB0, gB1, K, (c + 2) * BKT, tid);
        CP_COMMIT();

        uint32_t s0 = sbase + (uint32_t)((c % 3) * 4 * TILE_BYTES);
        #pragma unroll
        for (int kb = 0; kb < BKT; kb += 16) {
            uint32_t a0f[4][4], a1f[4][4], b0f[2][4], b1f[2][4];
            int aq = (kb + ak) >> 3;
            int bq = (kb + bk) >> 3;
            #pragma unroll
            for (int mt = 0; mt < 4; mt++) {
                int r = wm * 64 + mt * 16 + ar;
                uint32_t ad = s0 + SWZ(r, aq);
                ldsm4(a0f[mt], ad);
                ldsm4(a1f[mt], ad + TILE_BYTES);
            }
            #pragma unroll
            for (int nt = 0; nt < 2; nt++) {
                int r = wn * 32 + nt * 16 + br;
                uint32_t bd = s0 + 2 * TILE_BYTES + SWZ(r, bq);
                ldsm4(b0f[nt], bd);
                ldsm4(b1f[nt], bd + TILE_BYTES);
            }
            #pragma unroll
            for (int mt = 0; mt < 4; mt++)
                #pragma unroll
                for (int n8 = 0; n8 < 4; n8++) {
                    const uint32_t* b = &b0f[n8 >> 1][(n8 & 1) * 2];
                    mma16816(acc[mt][n8], a0f[mt], b);
                    mma16816(acc[mt][n8], a1f[mt], b);
                    mma16816(acc[mt][n8], a0f[mt], &b1f[n8 >> 1][(n8 & 1) * 2]);
                }
        }
    }

    // ---- epilogue (direct tile) ----
    long zC = zb * sC;
    int rb = lane >> 2;
    int cb = (lane & 3) * 2;
    #pragma unroll
    for (int mt = 0; mt < 4; mt++) {
        #pragma unroll
        for (int n8 = 0; n8 < 4; n8++) {
            long col = n0 + wn * 32 + n8 * 8 + cb;
            #pragma unroll
            for (int h = 0; h < 2; h++) {
                long row = m0 + wm * 64 + mt * 16 + rb + h * 8;
                *reinterpret_cast<float2*>(Cf + zC + row * (long)N + col) =
                    make_float2(acc[mt][n8][h * 2 + 0], acc[mt][n8][h * 2 + 1]);
            }
        }
    }

    // ---- mirror transposed tile at (pn, pm) ----
    if (pm != pn) {
        __syncthreads();
        float* stg = reinterpret_cast<float*>(smem);   // 128 x 129 floats
        #pragma unroll
        for (int mt = 0; mt < 4; mt++)
            #pragma unroll
            for (int n8 = 0; n8 < 4; n8++) {
                int colb = wn * 32 + n8 * 8 + cb;
                #pragma unroll
                for (int h = 0; h < 2; h++) {
                    int rowb = wm * 64 + mt * 16 + rb + h * 8;
                    stg[rowb * 129 + colb]     = acc[mt][n8][h * 2 + 0];
                    stg[rowb * 129 + colb + 1] = acc[mt][n8][h * 2 + 1];
                }
            }
        __syncthreads();
        #pragma unroll
        for (int it = 0; it < 64; it++) {
            int idx = tid + it * 256;
            int rr = idx >> 7, cc = idx & 127;
            Cf[zC + (n0 + rr) * (long)N + m0 + cc] = stg[cc * 129 + rr];
        }
    }
}

// ---------------------------------------------------------------------------
// 1-term HMMA GEMM (attended, FFN1, FFN2): 2 CTAs/SM, CTA 128x128, BK=64,
// 8 warps, 3 stages (96 KB/CTA).  OUT=0: fp32.  OUT=1: fp16 hi.  Batched via z.
// ---------------------------------------------------------------------------
#define F2_STAGE (2 * TILE_BYTES)      // A tile + B tile = 32 KB
#define F2_SMEM  (3 * F2_STAGE)        // 98304

__device__ __forceinline__ void load_chunk_1t(uint32_t sbase, int st,
    const __half* __restrict__ gA, const __half* __restrict__ gB,
    int K, int k0, int tid)
{
    uint32_t s0 = sbase + (uint32_t)(st * F2_STAGE);
    #pragma unroll
    for (int it = 0; it < 4; it++) {
        int idx = tid + it * 256;
        int r = idx >> 3, c = idx & 7;
        uint32_t so = SWZ(r, c);
        long go = (long)r * K + k0 + c * 8;
        CP_ASYNC16(s0 + so, gA + go);
        CP_ASYNC16(s0 + TILE_BYTES + so, gB + go);
    }
}

template<int OUT, bool BIAS, bool RELU>
__global__ __launch_bounds__(256, 2)
void hgemm_1t(const __half* __restrict__ A0, const __half* __restrict__ B0,
              const float* __restrict__ bias,
              float* __restrict__ Cf, __half* __restrict__ Chi,
              int M, int N, int K, long sA, long sB, long sC, int ntm)
{
    extern __shared__ char smem[];
    const uint32_t sbase = smem_u32(smem);
    const int tid  = threadIdx.x;
    const int wid  = tid >> 5, lane = tid & 31;
    const int wm   = wid & 1,  wn   = wid >> 1;

    int pm = blockIdx.x % ntm, pn = blockIdx.x / ntm;
    long m0 = (long)pm * 128, n0 = (long)pn * 128;
    long zb = blockIdx.z;
    const __half* gA = A0 + zb * sA + m0 * K;
    const __half* gB = B0 + zb * sB + n0 * K;

    float acc[4][4][4];
    #pragma unroll
    for (int i = 0; i < 4; i++)
        #pragma unroll
        for (int j = 0; j < 4; j++)
            #pragma unroll
            for (int k = 0; k < 4; k++) acc[i][j][k] = 0.f;

    const int ar = lane & 15;
    const int ak = (lane >> 4) << 3;
    const int br = ((lane >> 4) << 3) + (lane & 7);
    const int bk = ((lane >> 3) & 1) << 3;

    load_chunk_1t(sbase, 0, gA, gB, K, 0, tid);    CP_COMMIT();
    load_chunk_1t(sbase, 1, gA, gB, K, BKT, tid);  CP_COMMIT();

    const int nc = K / BKT;
    for (int c = 0; c < nc; c++) {
        CP_WAIT1();
        __syncthreads();
        if (c + 2 < nc)
            load_chunk_1t(sbase, (c + 2) % 3, gA, gB, K, (c + 2) * BKT, tid);
        CP_COMMIT();

        uint32_t s0 = sbase + (uint32_t)((c % 3) * F2_STAGE);
        #pragma unroll
        for (int kb = 0; kb < BKT; kb += 16) {
            uint32_t af[4][4], bf[2][4];
            int aq = (kb + ak) >> 3;
            int bq = (kb + bk) >> 3;
            #pragma unroll
            for (int mt = 0; mt < 4; mt++) {
                int r = wm * 64 + mt * 16 + ar;
                ldsm4(af[mt], s0 + SWZ(r, aq));
            }
            #pragma unroll
            for (int nt = 0; nt < 2; nt++) {
                int r = wn * 32 + nt * 16 + br;
                ldsm4(bf[nt], s0 + TILE_BYTES + SWZ(r, bq));
            }
            #pragma unroll
            for (int mt = 0; mt < 4; mt++)
                #pragma unroll
                for (int n8 = 0; n8 < 4; n8++)
                    mma16816(acc[mt][n8], af[mt], &bf[n8 >> 1][(n8 & 1) * 2]);
        }
    }

    // ---- epilogue ----
    long zC = zb * sC;
    int rb = lane >> 2;
    int cb = (lane & 3) * 2;
    #pragma unroll
    for (int mt = 0; mt < 4; mt++) {
        #pragma unroll
        for (int n8 = 0; n8 < 4; n8++) {
            long col = n0 + wn * 32 + n8 * 8 + cb;
            float bv0 = 0.f, bv1 = 0.f;
            if (BIAS) { bv0 = bias[col]; bv1 = bias[col + 1]; }
            #pragma unroll
            for (int h = 0; h < 2; h++) {
                long row = m0 + wm * 64 + mt * 16 + rb + h * 8;
                float v0 = acc[mt][n8][h * 2 + 0] + bv0;
                float v1 = acc[mt][n8][h * 2 + 1] + bv1;
                if (RELU) { v0 = fmaxf(v0, 0.f); v1 = fmaxf(v1, 0.f); }
                long o = row * (long)N + col;
                if (OUT == 0) {
                    *reinterpret_cast<float2*>(Cf + zC + o) = make_float2(v0, v1);
                } else {
                    *reinterpret_cast<__half2*>(Chi + zC + o) =
                        __halves2half2(__float2half_rn(v0), __float2half_rn(v1));
                }
            }
        }
    }
}

// ---------------------------------------------------------------------------
// Launch
// ---------------------------------------------------------------------------
extern "C" void kernel_launch(void* const* d_in, const int* in_sizes, int n_in,
                              void* d_out, int out_size) {
    const int*   ids = (const int*)  d_in[0];
    const float* emb = (const float*)d_in[1];
    const float* W1  = (const float*)d_in[2];
    const float* b1  = (const float*)d_in[3];
    const float* W2  = (const float*)d_in[4];
    const float* b2  = (const float*)d_in[5];
    float* out = (float*)d_out;

    float* scores;
    __half *xhi, *xlo, *xThi, *whi, *athi, *hdhi, *w1t, *w2t;
    cudaGetSymbolAddress((void**)&scores, g_scores);
    cudaGetSymbolAddress((void**)&xhi,    g_xhi);
    cudaGetSymbolAddress((void**)&xlo,    g_xlo);
    cudaGetSymbolAddress((void**)&xThi,   g_xThi);
    cudaGetSymbolAddress((void**)&whi,    g_whi);
    cudaGetSymbolAddress((void**)&athi,   g_atthi);
    cudaGetSymbolAddress((void**)&hdhi,   g_hidhi);
    cudaGetSymbolAddress((void**)&w1t,    g_W1t);
    cudaGetSymbolAddress((void**)&w2t,    g_W2t);

    const int SM3 = 4 * 3 * TILE_BYTES;   // scores: 196608
    cudaFuncSetAttribute(hgemm_sym, cudaFuncAttributeMaxDynamicSharedMemorySize, SM3);
    cudaFuncSetAttribute(hgemm_1t<1, false, false>, cudaFuncAttributeMaxDynamicSharedMemorySize, F2_SMEM);
    cudaFuncSetAttribute(hgemm_1t<1, true,  true >, cudaFuncAttributeMaxDynamicSharedMemorySize, F2_SMEM);
    cudaFuncSetAttribute(hgemm_1t<0, true,  false>, cudaFuncAttributeMaxDynamicSharedMemorySize, F2_SMEM);

    // 0) embedding -> x hi/lo fp16
    embed_kernel<<<BATCH * SEQ, 256>>>(ids, emb, xhi, xlo);

    // 1) xT single fp16 via gather-transpose from emb
    {
        dim3 grid(EMBED / 32, SEQ / 32, BATCH);
        xt_gather_kernel<<<grid, dim3(16, 16)>>>(ids, emb, xThi);
    }
    // 2) W1t + W2t single fp16 (combined, vectorized)
    {
        dim3 grid(VOCAB / 32, HID / 32, 2);
        transpose_weights_kernel<<<grid, dim3(16, 16)>>>(W1, W2, w1t, w2t);
    }

    // 3) scores = x @ x^T  (3-term symmetric, upper-tri + mirror)  M=N=2048 K=1024
    {
        const int ntm = SEQ / BMT;                 // 16
        dim3 grid(ntm * (ntm + 1) / 2, 1, BATCH);  // 136
        hgemm_sym<<<grid, 256, SM3>>>(
            xhi, xlo, scores, SEQ, EMBED, (long)SEQ * EMBED, (long)SEQ * SEQ, ntm);
    }

    // 4) softmax -> w hi
    softmax_kernel<<<BATCH * SEQ, 256>>>(scores, whi);

    // 5) attended = w @ x  (1-term, 2CTA/SM, fp16 hi out)  M=2048 N=1024 K=2048
    {
        dim3 grid((SEQ / 128) * (EMBED / 128), 1, BATCH);
        hgemm_1t<1, false, false><<<grid, 256, F2_SMEM>>>(
            whi, xThi, nullptr, nullptr, athi,
            SEQ, EMBED, SEQ,
            (long)SEQ * SEQ, (long)EMBED * SEQ, (long)SEQ * EMBED,
            SEQ / 128);
    }

    // 6) hidden = relu(att @ W1 + b1)  (1-term, 2CTA/SM, fp16 hi out)  M=8192 N=4096 K=1024
    {
        dim3 grid(((BATCH * SEQ) / 128) * (HID / 128), 1, 1);
        hgemm_1t<1, true, true><<<grid, 256, F2_SMEM>>>(
            athi, w1t, b1, nullptr, hdhi,
            BATCH * SEQ, HID, EMBED, 0, 0, 0,
            (BATCH * SEQ) / 128);
    }

    // 7) logits = hidden @ W2 + b2  (1-term, 2CTA/SM, fp32 out)  M=8192 N=32000 K=4096
    {
        dim3 grid(((BATCH * SEQ) / 128) * (VOCAB / 128), 1, 1);
        hgemm_1t<0, true, false><<<grid, 256, F2_SMEM>>>(
            hdhi, w2t, b2, out, nullptr,
            BATCH * SEQ, VOCAB, HID, 0, 0, 0,
            (BATCH * SEQ) / 128);
    }
}